// round 13
// baseline (speedup 1.0000x reference)
#include <cuda_runtime.h>
#include <cuda_fp16.h>
#include <math.h>
#include <stdint.h>

#define BB 256
#define SS 512
#define FF 64
#define HH 256
#define EE 128
#define G4H 1024
#define BT 16
#define KPE 328
#define KPD 264

// ---------------- device scratch ----------------
__device__ __half g_Hh[(size_t)SS * BB * HH];   // fp16 hi, [t][b][h] (enc then dec)
__device__ __half g_Hl[(size_t)SS * BB * HH];   // fp16 lo
__device__ __half g_xh[(size_t)BB * SS * FF];
__device__ __half g_xl[(size_t)BB * SS * FF];
__device__ float g_scorep[8 * BB * SS];
__device__ float g_wt[BB * SS];
__device__ float g_ctxp[8 * BB * HH];
__device__ float g_Wcomb[G4H * HH];
__device__ float g_bcomb[G4H];
__device__ float g_decH0[BB * HH];
__device__ float g_decC0[BB * HH];
__device__ float g_delta0[BB * G4H];
__device__ unsigned g_bar[32];

__device__ __forceinline__ float sigf(float v) { return 1.f / (1.f + __expf(-v)); }
__device__ __forceinline__ float ftanh(float v) {
    float e = __expf(-2.f * fabsf(v));
    float r = __fdividef(1.f - e, 1.f + e);
    return copysignf(r, v);
}

__device__ __forceinline__ void split2h(float v, __half& h, __half& l) {
    h = __float2half_rn(v);
    l = __float2half_rn(v - __half2float(h));
}

__device__ __forceinline__ void ldm4(uint32_t* r, const void* p) {
    unsigned a = (unsigned)__cvta_generic_to_shared(p);
    asm volatile("ldmatrix.sync.aligned.m8n8.x4.shared.b16 {%0,%1,%2,%3}, [%4];"
                 : "=r"(r[0]), "=r"(r[1]), "=r"(r[2]), "=r"(r[3]) : "r"(a));
}

__device__ __forceinline__ void mma16816(float* d, const uint32_t* a, uint32_t b0, uint32_t b1) {
    asm volatile("mma.sync.aligned.m16n8k16.row.col.f32.f16.f16.f32 "
                 "{%0,%1,%2,%3}, {%4,%5,%6,%7}, {%8,%9}, {%0,%1,%2,%3};"
                 : "+f"(d[0]), "+f"(d[1]), "+f"(d[2]), "+f"(d[3])
                 : "r"(a[0]), "r"(a[1]), "r"(a[2]), "r"(a[3]), "r"(b0), "r"(b1));
}

__device__ __forceinline__ void rel_inc(unsigned* p) {
    asm volatile("red.release.gpu.global.add.u32 [%0], %1;" :: "l"(p), "r"(1u) : "memory");
}
__device__ __forceinline__ unsigned acq_ld(unsigned* p) {
    unsigned v;
    asm volatile("ld.acquire.gpu.global.u32 %0, [%1];" : "=r"(v) : "l"(p) : "memory");
    return v;
}

// ---------------- K0x: split x into fp16 hi/lo ----------------
__global__ void k0x(const float* __restrict__ x) {
    size_t idx = (size_t)blockIdx.x * 256 + threadIdx.x;
    float4 v = ((const float4*)x)[idx];
    __half h0, l0, h1, l1, h2, l2, h3, l3;
    split2h(v.x, h0, l0); split2h(v.y, h1, l1); split2h(v.z, h2, l2); split2h(v.w, h3, l3);
    ((__half2*)g_xh)[idx * 2]     = __halves2half2(h0, h1);
    ((__half2*)g_xh)[idx * 2 + 1] = __halves2half2(h2, h3);
    ((__half2*)g_xl)[idx * 2]     = __halves2half2(l0, l1);
    ((__half2*)g_xl)[idx * 2 + 1] = __halves2half2(l2, l3);
}

// ---------------- K0: decoder combined weights + zero barriers ----------------
__global__ void k0_prep(const float* __restrict__ dec_Wih, const float* __restrict__ dec_Whh,
                        const float* __restrict__ dec_bih, const float* __restrict__ dec_bhh,
                        const float* __restrict__ out_W, const float* __restrict__ out_b) {
    int row = blockIdx.x;
    int col = threadIdx.x;
    __shared__ float wi[FF];
    if (col < FF) wi[col] = dec_Wih[row * FF + col];
    __syncthreads();
    float acc = dec_Whh[row * HH + col];
#pragma unroll 8
    for (int f = 0; f < FF; f++) acc += wi[f] * out_W[f * HH + col];
    g_Wcomb[row * HH + col] = acc;
    if (col == 0) {
        float b = dec_bih[row] + dec_bhh[row];
        for (int f = 0; f < FF; f++) b += wi[f] * out_b[f];
        g_bcomb[row] = b;
    }
    if (row == 0 && col < 32) g_bar[col] = 0u;
}

// ---------------- K1: encoder recurrence (512 thr, fp16 2-term, B regs, eager release) ----------------
__global__ __launch_bounds__(512, 1)
void k1_enc(const float* __restrict__ Wih, const float* __restrict__ Whh,
            const float* __restrict__ bih, const float* __restrict__ bhh,
            const float* __restrict__ attn_W) {
    extern __shared__ char smc[];
    __half* wh = (__half*)smc;              // [128][KPE] (init only)
    __half* ah = wh + 128 * KPE;            // [16][KPE]
    __half* al = ah + 16 * KPE;
    float* gates0 = (float*)(al + 16 * KPE);   // [16][132]
    float* gates1 = gates0 + 16 * 132;

    const int tid = threadIdx.x;
    const int ng = blockIdx.x & 7, bg = blockIdx.x >> 3;
    const int lane = tid & 31, w = tid >> 5;
    const int wsub = w & 7, wg = w >> 3;

    // weights (fp16) -> smem, then hoist B fragments to registers
    {
        int n = tid >> 2, quarter = tid & 3;
        int jj = n >> 2, g = n & 3;
        int grow = g * HH + ng * 32 + jj;
        for (int k = quarter * 80; k < quarter * 80 + 80; k++) {
            float wv = (k < HH) ? Whh[grow * HH + k] : Wih[grow * FF + (k - HH)];
            wh[n * KPE + k] = __float2half_rn(wv);
        }
    }
    __syncthreads();
    const int kbase = wg * 160;
    const int rB = wsub * 16 + (lane & 7) + ((lane >= 16) ? 8 : 0);
    const int cB = (lane & 8) ? 8 : 0;
    const __half* bph = wh + rB * KPE + cB + kbase;
    uint32_t Bf[10][4];
#pragma unroll
    for (int ks = 0; ks < 10; ks++) ldm4(Bf[ks], bph + ks * 16);

    const int b_loc = w;
    const int j = lane;
    const int col = ng * 32 + j;
    float bias[4];
#pragma unroll
    for (int g = 0; g < 4; g++) bias[g] = bih[g * HH + col] + bhh[g * HH + col];
    const float aw_j = attn_W[col];

    const int rA = (lane & 7) + ((lane & 8) ? 8 : 0);
    const int cA = (lane >> 4) * 8;
    const __half* aph = ah + rA * KPE + cA + kbase;
    const __half* apl = al + rA * KPE + cA + kbase;

    // x-prefetch addressing: tid<256 handles one 16B chunk (hi or lo)
    const int xb = tid >> 4, xc = tid & 15;

    float c0 = 0.f;
    unsigned* ctr = &g_bar[bg];
    float* mygates = wg ? gates1 : gates0;

    for (int t = 0; t < SS; t++) {
        // prefetch x(t) into registers BEFORE poll (flag-independent)
        uint4 xv;
        if (tid < 256) {
            size_t off = ((size_t)(bg * BT + xb) * SS + t) * FF;
            xv = (xc < 8) ? ((const uint4*)(g_xh + off))[xc]
                          : ((const uint4*)(g_xl + off))[xc - 8];
        }
        if (t > 0 && tid == 0) {
            unsigned tgt = 128u * (unsigned)t;
            while (acq_ld(ctr) < tgt) {}
        }
        __syncthreads();
        // A-build h region: 16 rows x 32 chunks (hi & lo)
        for (int idx = tid; idx < 16 * 32; idx += 512) {
            int b = idx >> 5, q = idx & 31;
            uint4 vh, vl;
            if (t > 0) {
                size_t off = ((size_t)(t - 1) * BB + bg * BT + b) * HH;
                vh = ((const uint4*)(g_Hh + off))[q];
                vl = ((const uint4*)(g_Hl + off))[q];
            } else {
                vh = make_uint4(0, 0, 0, 0); vl = make_uint4(0, 0, 0, 0);
            }
            *(uint4*)(ah + b * KPE + q * 8) = vh;
            *(uint4*)(al + b * KPE + q * 8) = vl;
        }
        // x region from prefetched regs
        if (tid < 256) {
            __half* dst = ((xc < 8) ? ah : al) + xb * KPE + (32 + (xc & 7)) * 8;
            *(uint4*)dst = xv;
        }
        __syncthreads();

        float dA0[4] = {0, 0, 0, 0}, dA1[4] = {0, 0, 0, 0};
        float dB0[4] = {0, 0, 0, 0}, dB1[4] = {0, 0, 0, 0};
#pragma unroll
        for (int ks = 0; ks < 10; ks++) {
            uint32_t A0[4], A1[4];
            ldm4(A0, aph + ks * 16);
            ldm4(A1, apl + ks * 16);
            mma16816(dA0, A0, Bf[ks][0], Bf[ks][1]);
            mma16816(dA1, A0, Bf[ks][2], Bf[ks][3]);
            mma16816(dB0, A1, Bf[ks][0], Bf[ks][1]);
            mma16816(dB1, A1, Bf[ks][2], Bf[ks][3]);
        }
        {
            int g = lane >> 2, tg = lane & 3;
            int cc = wsub * 16 + tg * 2;
            *(float2*)(mygates + g * 132 + cc)          = make_float2(dA0[0] + dB0[0], dA0[1] + dB0[1]);
            *(float2*)(mygates + (g + 8) * 132 + cc)    = make_float2(dA0[2] + dB0[2], dA0[3] + dB0[3]);
            *(float2*)(mygates + g * 132 + cc + 8)      = make_float2(dA1[0] + dB1[0], dA1[1] + dB1[1]);
            *(float2*)(mygates + (g + 8) * 132 + cc + 8)= make_float2(dA1[2] + dB1[2], dA1[3] + dB1[3]);
        }
        __syncthreads();
        {
            float4 gv0 = *(float4*)(gates0 + b_loc * 132 + j * 4);
            float4 gv1 = *(float4*)(gates1 + b_loc * 132 + j * 4);
            float i0 = sigf(gv0.x + gv1.x + bias[0]);
            float f0 = sigf(gv0.y + gv1.y + bias[1]);
            float gg0 = ftanh(gv0.z + gv1.z + bias[2]);
            float o0 = sigf(gv0.w + gv1.w + bias[3]);
            c0 = f0 * c0 + i0 * gg0;
            float hh0 = o0 * ftanh(c0);
            size_t oi = (size_t)t * BB * HH + (size_t)(bg * BT + b_loc) * HH + col;
            __half hv, lv;
            split2h(hh0, hv, lv);
            g_Hh[oi] = hv; g_Hl[oi] = lv;
            // eager per-warp release: this warp's 32 h values are stored
            __syncwarp();
            if (lane == 0) rel_inc(ctr);
            // attention score partial AFTER release (not release-protected)
            float s0 = hh0 * aw_j;
#pragma unroll
            for (int o = 16; o; o >>= 1) s0 += __shfl_xor_sync(~0u, s0, o);
            if (lane == 0)
                g_scorep[(size_t)ng * BB * SS + (size_t)(bg * BT + b_loc) * SS + t] = s0;
        }
    }
}

// ---------------- K2a: softmax ----------------
__global__ __launch_bounds__(256)
void k2a_softmax(const float* __restrict__ attn_b, float* __restrict__ out_wt) {
    int b = blockIdx.x, tid = threadIdx.x;
    __shared__ float sc[SS];
    __shared__ float red[8];
    const float ab = attn_b[0];
    for (int tt = tid; tt < SS; tt += 256) {
        float s = ab;
#pragma unroll
        for (int ng = 0; ng < 8; ng++)
            s += g_scorep[(size_t)ng * BB * SS + (size_t)b * SS + tt];
        sc[tt] = s;
    }
    __syncthreads();
    float m = -1e30f;
    for (int tt = tid; tt < SS; tt += 256) m = fmaxf(m, sc[tt]);
    for (int o = 16; o; o >>= 1) m = fmaxf(m, __shfl_xor_sync(~0u, m, o));
    if ((tid & 31) == 0) red[tid >> 5] = m;
    __syncthreads();
    if (tid < 8) {
        float mm = red[tid];
        for (int o = 4; o; o >>= 1) mm = fmaxf(mm, __shfl_xor_sync(0xff, mm, o));
        if (tid == 0) red[0] = mm;
    }
    __syncthreads();
    m = red[0];
    __syncthreads();
    float lsum = 0.f;
    for (int tt = tid; tt < SS; tt += 256) { float e = expf(sc[tt] - m); sc[tt] = e; lsum += e; }
    for (int o = 16; o; o >>= 1) lsum += __shfl_xor_sync(~0u, lsum, o);
    if ((tid & 31) == 0) red[tid >> 5] = lsum;
    __syncthreads();
    if (tid < 8) {
        float ss = red[tid];
        for (int o = 4; o; o >>= 1) ss += __shfl_xor_sync(0xff, ss, o);
        if (tid == 0) red[0] = ss;
    }
    __syncthreads();
    float inv = 1.f / red[0];
    for (int tt = tid; tt < SS; tt += 256) {
        float wv = sc[tt] * inv;
        g_wt[b * SS + tt] = wv;
        out_wt[b * SS + tt] = wv;
    }
}

// ---------------- K2b: context partials ----------------
__global__ __launch_bounds__(256)
void k2b_ctx() {
    int b = blockIdx.x & 255, ch = blockIdx.x >> 8, tid = threadIdx.x;
    __shared__ float ws[64];
    if (tid < 64) ws[tid] = g_wt[b * SS + ch * 64 + tid];
    __syncthreads();
    float ca = 0.f;
#pragma unroll 4
    for (int i = 0; i < 64; i++) {
        int t2 = ch * 64 + i;
        size_t off = (size_t)t2 * BB * HH + (size_t)b * HH + tid;
        ca += ws[i] * (__half2float(g_Hh[off]) + __half2float(g_Hl[off]));
    }
    g_ctxp[(size_t)ch * BB * HH + b * HH + tid] = ca;
}

// ---------------- K2c: reduce context + embedding + decoder init + delta0 ----------------
__global__ __launch_bounds__(256)
void k2c_emb(const float* __restrict__ fc_W, const float* __restrict__ fc_b,
             const float* __restrict__ bn_g, const float* __restrict__ bn_be,
             const float* __restrict__ bn_m, const float* __restrict__ bn_v,
             const float* __restrict__ dh_W, const float* __restrict__ dh_b,
             const float* __restrict__ dc_W, const float* __restrict__ dc_b,
             const float* __restrict__ dec_Wih, const float* __restrict__ out_W,
             const float* __restrict__ out_b,
             float* __restrict__ out_emb) {
    int b = blockIdx.x, tid = threadIdx.x;
    __shared__ float ctx[HH];
    __shared__ float embs[EE];
    __shared__ float dhs[HH];
    __shared__ float v0s[FF];
    {
        float ca = 0.f;
#pragma unroll
        for (int ch = 0; ch < 8; ch++) ca += g_ctxp[(size_t)ch * BB * HH + b * HH + tid];
        ctx[tid] = ca;
    }
    __syncthreads();
    if (tid < EE) {
        float r = fc_b[tid];
#pragma unroll 8
        for (int k = 0; k < HH; k++) r += ctx[k] * fc_W[tid * HH + k];
        float em = tanhf((r - bn_m[tid]) * rsqrtf(bn_v[tid] + 1e-5f) * bn_g[tid] + bn_be[tid]);
        embs[tid] = em;
        out_emb[b * EE + tid] = em;
    }
    __syncthreads();
    {
        float dh = dh_b[tid], dc = dc_b[tid];
#pragma unroll 8
        for (int e = 0; e < EE; e++) { dh += embs[e] * dh_W[tid * EE + e]; dc += embs[e] * dc_W[tid * EE + e]; }
        g_decH0[b * HH + tid] = dh;
        g_decC0[b * HH + tid] = dc;
        dhs[tid] = dh;
    }
    __syncthreads();
    if (tid < FF) {
        float v = out_b[tid];
#pragma unroll 8
        for (int h = 0; h < HH; h++) v += dhs[h] * out_W[tid * HH + h];
        v0s[tid] = v;
    }
    __syncthreads();
    for (int row = tid; row < G4H; row += 256) {
        float d = 0.f;
#pragma unroll 8
        for (int f = 0; f < FF; f++) d += v0s[f] * dec_Wih[row * FF + f];
        g_delta0[b * G4H + row] = d;
    }
}

// ---------------- K3: decoder recurrence (512 thr, fp16 2-term, B regs, eager release) ----------------
__global__ __launch_bounds__(512, 1)
void k3_dec() {
    extern __shared__ char smc[];
    __half* wh = (__half*)smc;              // [128][KPD] (init only)
    __half* ah = wh + 128 * KPD;            // [16][KPD]
    __half* al = ah + 16 * KPD;
    float* gates0 = (float*)(al + 16 * KPD);
    float* gates1 = gates0 + 16 * 132;

    const int tid = threadIdx.x;
    const int ng = blockIdx.x & 7, bg = blockIdx.x >> 3;
    const int lane = tid & 31, w = tid >> 5;
    const int wsub = w & 7, wg = w >> 3;

    {
        int n = tid >> 2, quarter = tid & 3;
        int jj = n >> 2, g = n & 3;
        int grow = g * HH + ng * 32 + jj;
        for (int k = quarter * 64; k < quarter * 64 + 64; k++) {
            wh[n * KPD + k] = __float2half_rn(g_Wcomb[grow * HH + k]);
        }
    }
    __syncthreads();
    const int kbase = wg * 128;
    const int rB = wsub * 16 + (lane & 7) + ((lane >= 16) ? 8 : 0);
    const int cB = (lane & 8) ? 8 : 0;
    const __half* bph = wh + rB * KPD + cB + kbase;
    uint32_t Bf[8][4];
#pragma unroll
    for (int ks = 0; ks < 8; ks++) ldm4(Bf[ks], bph + ks * 16);

    const int b_loc = w;
    const int j = lane;
    const int col = ng * 32 + j;
    float bias[4], d0v[4];
#pragma unroll
    for (int g = 0; g < 4; g++) {
        int row = g * HH + col;
        bias[g] = g_bcomb[row];
        d0v[g] = g_delta0[(bg * BT + b_loc) * G4H + row];
    }
    float c0 = g_decC0[(bg * BT + b_loc) * HH + col];

    const int rA = (lane & 7) + ((lane & 8) ? 8 : 0);
    const int cA = (lane >> 4) * 8;
    const __half* aph = ah + rA * KPD + cA + kbase;
    const __half* apl = al + rA * KPD + cA + kbase;

    unsigned* ctr = &g_bar[16 + bg];
    float* mygates = wg ? gates1 : gates0;

    for (int t = 0; t < SS; t++) {
        if (t > 0 && tid == 0) {
            unsigned tgt = 128u * (unsigned)t;
            while (acq_ld(ctr) < tgt) {}
        }
        __syncthreads();
        for (int idx = tid; idx < 16 * 32; idx += 512) {
            int b = idx >> 5, q = idx & 31;
            if (t > 0) {
                size_t off = ((size_t)(t - 1) * BB + bg * BT + b) * HH;
                *(uint4*)(ah + b * KPD + q * 8) = ((const uint4*)(g_Hh + off))[q];
                *(uint4*)(al + b * KPD + q * 8) = ((const uint4*)(g_Hl + off))[q];
            } else {
                const float* p = g_decH0 + (size_t)(bg * BT + b) * HH + q * 8;
#pragma unroll
                for (int e = 0; e < 8; e++) {
                    __half hv, lv; split2h(p[e], hv, lv);
                    ah[b * KPD + q * 8 + e] = hv;
                    al[b * KPD + q * 8 + e] = lv;
                }
            }
        }
        __syncthreads();

        float dA0[4] = {0, 0, 0, 0}, dA1[4] = {0, 0, 0, 0};
        float dB0[4] = {0, 0, 0, 0}, dB1[4] = {0, 0, 0, 0};
#pragma unroll
        for (int ks = 0; ks < 8; ks++) {
            uint32_t A0[4], A1[4];
            ldm4(A0, aph + ks * 16);
            ldm4(A1, apl + ks * 16);
            mma16816(dA0, A0, Bf[ks][0], Bf[ks][1]);
            mma16816(dA1, A0, Bf[ks][2], Bf[ks][3]);
            mma16816(dB0, A1, Bf[ks][0], Bf[ks][1]);
            mma16816(dB1, A1, Bf[ks][2], Bf[ks][3]);
        }
        {
            int g = lane >> 2, tg = lane & 3;
            int cc = wsub * 16 + tg * 2;
            *(float2*)(mygates + g * 132 + cc)          = make_float2(dA0[0] + dB0[0], dA0[1] + dB0[1]);
            *(float2*)(mygates + (g + 8) * 132 + cc)    = make_float2(dA0[2] + dB0[2], dA0[3] + dB0[3]);
            *(float2*)(mygates + g * 132 + cc + 8)      = make_float2(dA1[0] + dB1[0], dA1[1] + dB1[1]);
            *(float2*)(mygates + (g + 8) * 132 + cc + 8)= make_float2(dA1[2] + dB1[2], dA1[3] + dB1[3]);
        }
        __syncthreads();
        {
            float4 gv0 = *(float4*)(gates0 + b_loc * 132 + j * 4);
            float4 gv1 = *(float4*)(gates1 + b_loc * 132 + j * 4);
            float e00 = bias[0], e01 = bias[1], e02 = bias[2], e03 = bias[3];
            if (t == 0) { e00 -= d0v[0]; e01 -= d0v[1]; e02 -= d0v[2]; e03 -= d0v[3]; }
            float i0 = sigf(gv0.x + gv1.x + e00);
            float f0 = sigf(gv0.y + gv1.y + e01);
            float gg0 = ftanh(gv0.z + gv1.z + e02);
            float o0 = sigf(gv0.w + gv1.w + e03);
            c0 = f0 * c0 + i0 * gg0;
            float hh0 = o0 * ftanh(c0);
            size_t oi = (size_t)t * BB * HH + (size_t)(bg * BT + b_loc) * HH + col;
            __half hv, lv;
            split2h(hh0, hv, lv);
            g_Hh[oi] = hv; g_Hl[oi] = lv;
            __syncwarp();
            if (lane == 0) rel_inc(ctr);
        }
    }
}

// ---------------- K4: reconstruction GEMM ----------------
#define K4R 64
__global__ __launch_bounds__(256)
void k4_out(const float* __restrict__ out_W, const float* __restrict__ out_b,
            float* __restrict__ rec) {
    extern __shared__ float sm[];
    float* ws = sm;              // [k][f]
    float* hs = sm + HH * FF;    // [k][r] stride 65
    const int tid = threadIdx.x;
    const int m0 = blockIdx.x * K4R;
    for (int idx = tid; idx < HH * FF; idx += 256) {
        int k = idx >> 6, f = idx & 63;
        ws[idx] = out_W[f * HH + k];
    }
    for (int idx = tid; idx < K4R * (HH / 2); idx += 256) {
        int r = idx >> 7, kk = (idx & 127) * 2;
        size_t off = (size_t)(m0 + r) * HH + kk;
        __half2 vh = *(const __half2*)(g_Hh + off);
        __half2 vl = *(const __half2*)(g_Hl + off);
        hs[kk * 65 + r]       = __half2float(__low2half(vh)) + __half2float(__low2half(vl));
        hs[(kk + 1) * 65 + r] = __half2float(__high2half(vh)) + __half2float(__high2half(vl));
    }
    __syncthreads();
    const int rg = tid >> 4, cg = tid & 15;
    float acc[4][4];
#pragma unroll
    for (int r = 0; r < 4; r++)
#pragma unroll
        for (int c = 0; c < 4; c++) acc[r][c] = 0.f;
#pragma unroll 4
    for (int k = 0; k < HH; k++) {
        float4 wv = *(const float4*)(ws + k * FF + cg * 4);
        float h0 = hs[k * 65 + rg * 4 + 0];
        float h1 = hs[k * 65 + rg * 4 + 1];
        float h2 = hs[k * 65 + rg * 4 + 2];
        float h3 = hs[k * 65 + rg * 4 + 3];
        acc[0][0] += h0 * wv.x; acc[0][1] += h0 * wv.y; acc[0][2] += h0 * wv.z; acc[0][3] += h0 * wv.w;
        acc[1][0] += h1 * wv.x; acc[1][1] += h1 * wv.y; acc[1][2] += h1 * wv.z; acc[1][3] += h1 * wv.w;
        acc[2][0] += h2 * wv.x; acc[2][1] += h2 * wv.y; acc[2][2] += h2 * wv.z; acc[2][3] += h2 * wv.w;
        acc[3][0] += h3 * wv.x; acc[3][1] += h3 * wv.y; acc[3][2] += h3 * wv.z; acc[3][3] += h3 * wv.w;
    }
    float ob0 = out_b[cg * 4 + 0], ob1 = out_b[cg * 4 + 1], ob2 = out_b[cg * 4 + 2], ob3 = out_b[cg * 4 + 3];
    const int t = m0 >> 8;
    const int bbase = m0 & 255;
#pragma unroll
    for (int r = 0; r < 4; r++) {
        int bb = bbase + rg * 4 + r;
        float4 o = make_float4(acc[r][0] + ob0, acc[r][1] + ob1, acc[r][2] + ob2, acc[r][3] + ob3);
        *(float4*)&rec[((size_t)bb * SS + t) * FF + cg * 4] = o;
    }
}

// ---------------- launch ----------------
extern "C" void kernel_launch(void* const* d_in, const int* in_sizes, int n_in,
                              void* d_out, int out_size) {
    const float* x        = (const float*)d_in[0];
    const float* enc_Wih  = (const float*)d_in[1];
    const float* enc_Whh  = (const float*)d_in[2];
    const float* enc_bih  = (const float*)d_in[3];
    const float* enc_bhh  = (const float*)d_in[4];
    const float* attn_W   = (const float*)d_in[5];
    const float* attn_b   = (const float*)d_in[6];
    const float* fc_W     = (const float*)d_in[7];
    const float* fc_b     = (const float*)d_in[8];
    const float* bn_g     = (const float*)d_in[9];
    const float* bn_be    = (const float*)d_in[10];
    const float* bn_m     = (const float*)d_in[11];
    const float* bn_v     = (const float*)d_in[12];
    const float* dh_W     = (const float*)d_in[13];
    const float* dh_b     = (const float*)d_in[14];
    const float* dc_W     = (const float*)d_in[15];
    const float* dc_b     = (const float*)d_in[16];
    const float* dec_Wih  = (const float*)d_in[17];
    const float* dec_Whh  = (const float*)d_in[18];
    const float* dec_bih  = (const float*)d_in[19];
    const float* dec_bhh  = (const float*)d_in[20];
    const float* out_W    = (const float*)d_in[21];
    const float* out_b    = (const float*)d_in[22];

    float* out = (float*)d_out;
    float* out_rec = out;
    float* out_emb = out + (size_t)BB * SS * FF;
    float* out_wt  = out_emb + (size_t)BB * EE;

    const int smem1 = 128 * KPE * 2 + 2 * 16 * KPE * 2 + 2 * 16 * 132 * 4;   // 121856
    const int smem3 = 128 * KPD * 2 + 2 * 16 * KPD * 2 + 2 * 16 * 132 * 4;   // 101376
    const int smem4 = (HH * FF + HH * 65) * 4;
    cudaFuncSetAttribute(k1_enc, cudaFuncAttributeMaxDynamicSharedMemorySize, smem1);
    cudaFuncSetAttribute(k3_dec, cudaFuncAttributeMaxDynamicSharedMemorySize, smem3);
    cudaFuncSetAttribute(k4_out, cudaFuncAttributeMaxDynamicSharedMemorySize, smem4);

    k0x<<<(BB * SS * FF) / (256 * 4), 256>>>(x);
    k0_prep<<<G4H, 256>>>(dec_Wih, dec_Whh, dec_bih, dec_bhh, out_W, out_b);
    k1_enc<<<128, 512, smem1>>>(enc_Wih, enc_Whh, enc_bih, enc_bhh, attn_W);
    k2a_softmax<<<BB, 256>>>(attn_b, out_wt);
    k2b_ctx<<<8 * BB, 256>>>();
    k2c_emb<<<BB, 256>>>(fc_W, fc_b, bn_g, bn_be, bn_m, bn_v,
                         dh_W, dh_b, dc_W, dc_b, dec_Wih, out_W, out_b, out_emb);
    k3_dec<<<128, 512, smem3>>>();
    k4_out<<<(BB * SS) / K4R, 256, smem4>>>(out_W, out_b, out_rec);
}

// round 14
// speedup vs baseline: 1.0027x; 1.0027x over previous
#include <cuda_runtime.h>
#include <cuda_fp16.h>
#include <math.h>
#include <stdint.h>

#define BB 256
#define SS 512
#define FF 64
#define HH 256
#define EE 128
#define G4H 1024
#define BT 16
#define KPE 328
#define KPD 264

// ---------------- device scratch ----------------
__device__ __half g_Hh[(size_t)SS * BB * HH];   // fp16 hi, [t][b][h] (enc then dec)
__device__ __half g_Hl[(size_t)SS * BB * HH];   // fp16 lo
__device__ __half g_xh[(size_t)BB * SS * FF];
__device__ __half g_xl[(size_t)BB * SS * FF];
__device__ float g_scorep[8 * BB * SS];
__device__ float g_wt[BB * SS];
__device__ float g_ctxp[16 * BB * HH];
__device__ float g_Wcomb[G4H * HH];
__device__ float g_bcomb[G4H];
__device__ float g_decH0[BB * HH];
__device__ float g_decC0[BB * HH];
__device__ float g_delta0[BB * G4H];
__device__ unsigned g_bar[32];

__device__ __forceinline__ float sigf(float v) { return 1.f / (1.f + __expf(-v)); }
__device__ __forceinline__ float ftanh(float v) {
    float e = __expf(-2.f * fabsf(v));
    float r = __fdividef(1.f - e, 1.f + e);
    return copysignf(r, v);
}

__device__ __forceinline__ void split2h(float v, __half& h, __half& l) {
    h = __float2half_rn(v);
    l = __float2half_rn(v - __half2float(h));
}

__device__ __forceinline__ void ldm4(uint32_t* r, const void* p) {
    unsigned a = (unsigned)__cvta_generic_to_shared(p);
    asm volatile("ldmatrix.sync.aligned.m8n8.x4.shared.b16 {%0,%1,%2,%3}, [%4];"
                 : "=r"(r[0]), "=r"(r[1]), "=r"(r[2]), "=r"(r[3]) : "r"(a));
}

__device__ __forceinline__ void mma16816(float* d, const uint32_t* a, uint32_t b0, uint32_t b1) {
    asm volatile("mma.sync.aligned.m16n8k16.row.col.f32.f16.f16.f32 "
                 "{%0,%1,%2,%3}, {%4,%5,%6,%7}, {%8,%9}, {%0,%1,%2,%3};"
                 : "+f"(d[0]), "+f"(d[1]), "+f"(d[2]), "+f"(d[3])
                 : "r"(a[0]), "r"(a[1]), "r"(a[2]), "r"(a[3]), "r"(b0), "r"(b1));
}

__device__ __forceinline__ void rel_inc(unsigned* p) {
    asm volatile("red.release.gpu.global.add.u32 [%0], %1;" :: "l"(p), "r"(1u) : "memory");
}
__device__ __forceinline__ unsigned acq_ld(unsigned* p) {
    unsigned v;
    asm volatile("ld.acquire.gpu.global.u32 %0, [%1];" : "=r"(v) : "l"(p) : "memory");
    return v;
}

// ---------------- K0x: split x into fp16 hi/lo ----------------
__global__ void k0x(const float* __restrict__ x) {
    size_t idx = (size_t)blockIdx.x * 256 + threadIdx.x;
    float4 v = ((const float4*)x)[idx];
    __half h0, l0, h1, l1, h2, l2, h3, l3;
    split2h(v.x, h0, l0); split2h(v.y, h1, l1); split2h(v.z, h2, l2); split2h(v.w, h3, l3);
    ((__half2*)g_xh)[idx * 2]     = __halves2half2(h0, h1);
    ((__half2*)g_xh)[idx * 2 + 1] = __halves2half2(h2, h3);
    ((__half2*)g_xl)[idx * 2]     = __halves2half2(l0, l1);
    ((__half2*)g_xl)[idx * 2 + 1] = __halves2half2(l2, l3);
}

// ---------------- K0: decoder combined weights + zero barriers ----------------
__global__ void k0_prep(const float* __restrict__ dec_Wih, const float* __restrict__ dec_Whh,
                        const float* __restrict__ dec_bih, const float* __restrict__ dec_bhh,
                        const float* __restrict__ out_W, const float* __restrict__ out_b) {
    int row = blockIdx.x;
    int col = threadIdx.x;
    __shared__ float wi[FF];
    if (col < FF) wi[col] = dec_Wih[row * FF + col];
    __syncthreads();
    float acc = dec_Whh[row * HH + col];
#pragma unroll 8
    for (int f = 0; f < FF; f++) acc += wi[f] * out_W[f * HH + col];
    g_Wcomb[row * HH + col] = acc;
    if (col == 0) {
        float b = dec_bih[row] + dec_bhh[row];
        for (int f = 0; f < FF; f++) b += wi[f] * out_b[f];
        g_bcomb[row] = b;
    }
    if (row == 0 && col < 32) g_bar[col] = 0u;
}

// ---------------- K1: encoder recurrence, 512 threads, fp16 2-term, B in registers ----------------
__global__ __launch_bounds__(512, 1)
void k1_enc(const float* __restrict__ Wih, const float* __restrict__ Whh,
            const float* __restrict__ bih, const float* __restrict__ bhh,
            const float* __restrict__ attn_W) {
    extern __shared__ char smc[];
    __half* wh = (__half*)smc;              // [128][KPE] (init only)
    __half* ah = wh + 128 * KPE;            // [16][KPE]
    __half* al = ah + 16 * KPE;
    float* gates0 = (float*)(al + 16 * KPE);   // [16][132]
    float* gates1 = gates0 + 16 * 132;

    const int tid = threadIdx.x;
    const int ng = blockIdx.x & 7, bg = blockIdx.x >> 3;
    const int lane = tid & 31, w = tid >> 5;
    const int wsub = w & 7, wg = w >> 3;

    // weights (fp16) -> smem, then hoist B fragments to registers
    {
        int n = tid >> 2, quarter = tid & 3;
        int jj = n >> 2, g = n & 3;
        int grow = g * HH + ng * 32 + jj;
        for (int k = quarter * 80; k < quarter * 80 + 80; k++) {
            float wv = (k < HH) ? Whh[grow * HH + k] : Wih[grow * FF + (k - HH)];
            wh[n * KPE + k] = __float2half_rn(wv);
        }
    }
    __syncthreads();
    const int kbase = wg * 160;
    const int rB = wsub * 16 + (lane & 7) + ((lane >= 16) ? 8 : 0);
    const int cB = (lane & 8) ? 8 : 0;
    const __half* bph = wh + rB * KPE + cB + kbase;
    uint32_t Bf[10][4];
#pragma unroll
    for (int ks = 0; ks < 10; ks++) ldm4(Bf[ks], bph + ks * 16);

    const int b_loc = w;
    const int j = lane;
    const int col = ng * 32 + j;
    float bias[4];
#pragma unroll
    for (int g = 0; g < 4; g++) bias[g] = bih[g * HH + col] + bhh[g * HH + col];
    const float aw_j = attn_W[col];

    const int rA = (lane & 7) + ((lane & 8) ? 8 : 0);
    const int cA = (lane >> 4) * 8;
    const __half* aph = ah + rA * KPE + cA + kbase;
    const __half* apl = al + rA * KPE + cA + kbase;

    float c0 = 0.f;
    unsigned* ctr = &g_bar[bg];
    float* mygates = wg ? gates1 : gates0;

    for (int t = 0; t < SS; t++) {
        if (t > 0 && tid == 0) {
            unsigned tgt = 8u * (unsigned)t;
            while (acq_ld(ctr) < tgt) {}
        }
        __syncthreads();
        // A-build: 16 rows x 40 chunks (hi & lo)
        for (int idx = tid; idx < 16 * 40; idx += 512) {
            int b = idx / 40, q = idx - b * 40;
            uint4 vh, vl;
            if (q < 32) {
                if (t > 0) {
                    size_t off = ((size_t)(t - 1) * BB + bg * BT + b) * HH;
                    vh = ((const uint4*)(g_Hh + off))[q];
                    vl = ((const uint4*)(g_Hl + off))[q];
                } else {
                    vh = make_uint4(0, 0, 0, 0); vl = make_uint4(0, 0, 0, 0);
                }
            } else {
                size_t off = ((size_t)(bg * BT + b) * SS + t) * FF;
                vh = ((const uint4*)(g_xh + off))[q - 32];
                vl = ((const uint4*)(g_xl + off))[q - 32];
            }
            *(uint4*)(ah + b * KPE + q * 8) = vh;
            *(uint4*)(al + b * KPE + q * 8) = vl;
        }
        __syncthreads();

        float dA0[4] = {0, 0, 0, 0}, dA1[4] = {0, 0, 0, 0};
        float dB0[4] = {0, 0, 0, 0}, dB1[4] = {0, 0, 0, 0};
#pragma unroll
        for (int ks = 0; ks < 10; ks++) {
            uint32_t A0[4], A1[4];
            ldm4(A0, aph + ks * 16);
            ldm4(A1, apl + ks * 16);
            mma16816(dA0, A0, Bf[ks][0], Bf[ks][1]);
            mma16816(dA1, A0, Bf[ks][2], Bf[ks][3]);
            mma16816(dB0, A1, Bf[ks][0], Bf[ks][1]);
            mma16816(dB1, A1, Bf[ks][2], Bf[ks][3]);
        }
        {
            int g = lane >> 2, tg = lane & 3;
            int cc = wsub * 16 + tg * 2;
            *(float2*)(mygates + g * 132 + cc)          = make_float2(dA0[0] + dB0[0], dA0[1] + dB0[1]);
            *(float2*)(mygates + (g + 8) * 132 + cc)    = make_float2(dA0[2] + dB0[2], dA0[3] + dB0[3]);
            *(float2*)(mygates + g * 132 + cc + 8)      = make_float2(dA1[0] + dB1[0], dA1[1] + dB1[1]);
            *(float2*)(mygates + (g + 8) * 132 + cc + 8)= make_float2(dA1[2] + dB1[2], dA1[3] + dB1[3]);
        }
        __syncthreads();
        {
            float4 gv0 = *(float4*)(gates0 + b_loc * 132 + j * 4);
            float4 gv1 = *(float4*)(gates1 + b_loc * 132 + j * 4);
            float i0 = sigf(gv0.x + gv1.x + bias[0]);
            float f0 = sigf(gv0.y + gv1.y + bias[1]);
            float gg0 = ftanh(gv0.z + gv1.z + bias[2]);
            float o0 = sigf(gv0.w + gv1.w + bias[3]);
            c0 = f0 * c0 + i0 * gg0;
            float hh0 = o0 * ftanh(c0);
            size_t oi = (size_t)t * BB * HH + (size_t)(bg * BT + b_loc) * HH + col;
            __half hv, lv;
            split2h(hh0, hv, lv);
            g_Hh[oi] = hv; g_Hl[oi] = lv;
            float s0 = hh0 * aw_j;
#pragma unroll
            for (int o = 16; o; o >>= 1) s0 += __shfl_xor_sync(~0u, s0, o);
            if (lane == 0)
                g_scorep[(size_t)ng * BB * SS + (size_t)(bg * BT + b_loc) * SS + t] = s0;
        }
        __syncthreads();
        if (tid == 0) rel_inc(ctr);
    }
}

// ---------------- K2a: softmax ----------------
__global__ __launch_bounds__(256)
void k2a_softmax(const float* __restrict__ attn_b, float* __restrict__ out_wt) {
    int b = blockIdx.x, tid = threadIdx.x;
    __shared__ float sc[SS];
    __shared__ float red[8];
    const float ab = attn_b[0];
    for (int tt = tid; tt < SS; tt += 256) {
        float s = ab;
#pragma unroll
        for (int ng = 0; ng < 8; ng++)
            s += g_scorep[(size_t)ng * BB * SS + (size_t)b * SS + tt];
        sc[tt] = s;
    }
    __syncthreads();
    float m = -1e30f;
    for (int tt = tid; tt < SS; tt += 256) m = fmaxf(m, sc[tt]);
    for (int o = 16; o; o >>= 1) m = fmaxf(m, __shfl_xor_sync(~0u, m, o));
    if ((tid & 31) == 0) red[tid >> 5] = m;
    __syncthreads();
    if (tid < 8) {
        float mm = red[tid];
        for (int o = 4; o; o >>= 1) mm = fmaxf(mm, __shfl_xor_sync(0xff, mm, o));
        if (tid == 0) red[0] = mm;
    }
    __syncthreads();
    m = red[0];
    __syncthreads();
    float lsum = 0.f;
    for (int tt = tid; tt < SS; tt += 256) { float e = expf(sc[tt] - m); sc[tt] = e; lsum += e; }
    for (int o = 16; o; o >>= 1) lsum += __shfl_xor_sync(~0u, lsum, o);
    if ((tid & 31) == 0) red[tid >> 5] = lsum;
    __syncthreads();
    if (tid < 8) {
        float ss = red[tid];
        for (int o = 4; o; o >>= 1) ss += __shfl_xor_sync(0xff, ss, o);
        if (tid == 0) red[0] = ss;
    }
    __syncthreads();
    float inv = 1.f / red[0];
    for (int tt = tid; tt < SS; tt += 256) {
        float wv = sc[tt] * inv;
        g_wt[b * SS + tt] = wv;
        out_wt[b * SS + tt] = wv;
    }
}

// ---------------- K2b: context partials (16 t-chunks per batch) ----------------
__global__ __launch_bounds__(256)
void k2b_ctx() {
    int b = blockIdx.x & 255, ch = blockIdx.x >> 8, tid = threadIdx.x;
    __shared__ float ws[32];
    if (tid < 32) ws[tid] = g_wt[b * SS + ch * 32 + tid];
    __syncthreads();
    float ca = 0.f;
#pragma unroll 4
    for (int i = 0; i < 32; i++) {
        int t2 = ch * 32 + i;
        size_t off = (size_t)t2 * BB * HH + (size_t)b * HH + tid;
        ca += ws[i] * (__half2float(g_Hh[off]) + __half2float(g_Hl[off]));
    }
    g_ctxp[(size_t)ch * BB * HH + b * HH + tid] = ca;
}

// ---------------- K2c: reduce context + embedding + decoder init + delta0 ----------------
__global__ __launch_bounds__(256)
void k2c_emb(const float* __restrict__ fc_W, const float* __restrict__ fc_b,
             const float* __restrict__ bn_g, const float* __restrict__ bn_be,
             const float* __restrict__ bn_m, const float* __restrict__ bn_v,
             const float* __restrict__ dh_W, const float* __restrict__ dh_b,
             const float* __restrict__ dc_W, const float* __restrict__ dc_b,
             const float* __restrict__ dec_Wih, const float* __restrict__ out_W,
             const float* __restrict__ out_b,
             float* __restrict__ out_emb) {
    int b = blockIdx.x, tid = threadIdx.x;
    __shared__ float ctx[HH];
    __shared__ float embs[EE];
    __shared__ float dhs[HH];
    __shared__ float v0s[FF];
    {
        float ca = 0.f;
#pragma unroll
        for (int ch = 0; ch < 16; ch++) ca += g_ctxp[(size_t)ch * BB * HH + b * HH + tid];
        ctx[tid] = ca;
    }
    __syncthreads();
    if (tid < EE) {
        float r = fc_b[tid];
#pragma unroll 8
        for (int k = 0; k < HH; k++) r += ctx[k] * fc_W[tid * HH + k];
        float em = tanhf((r - bn_m[tid]) * rsqrtf(bn_v[tid] + 1e-5f) * bn_g[tid] + bn_be[tid]);
        embs[tid] = em;
        out_emb[b * EE + tid] = em;
    }
    __syncthreads();
    {
        float dh = dh_b[tid], dc = dc_b[tid];
#pragma unroll 8
        for (int e = 0; e < EE; e++) { dh += embs[e] * dh_W[tid * EE + e]; dc += embs[e] * dc_W[tid * EE + e]; }
        g_decH0[b * HH + tid] = dh;
        g_decC0[b * HH + tid] = dc;
        dhs[tid] = dh;
    }
    __syncthreads();
    if (tid < FF) {
        float v = out_b[tid];
#pragma unroll 8
        for (int h = 0; h < HH; h++) v += dhs[h] * out_W[tid * HH + h];
        v0s[tid] = v;
    }
    __syncthreads();
    for (int row = tid; row < G4H; row += 256) {
        float d = 0.f;
#pragma unroll 8
        for (int f = 0; f < FF; f++) d += v0s[f] * dec_Wih[row * FF + f];
        g_delta0[b * G4H + row] = d;
    }
}

// ---------------- K3: decoder recurrence, 512 threads, fp16 2-term, B in registers ----------------
__global__ __launch_bounds__(512, 1)
void k3_dec() {
    extern __shared__ char smc[];
    __half* wh = (__half*)smc;              // [128][KPD] (init only)
    __half* ah = wh + 128 * KPD;            // [16][KPD]
    __half* al = ah + 16 * KPD;
    float* gates0 = (float*)(al + 16 * KPD);
    float* gates1 = gates0 + 16 * 132;

    const int tid = threadIdx.x;
    const int ng = blockIdx.x & 7, bg = blockIdx.x >> 3;
    const int lane = tid & 31, w = tid >> 5;
    const int wsub = w & 7, wg = w >> 3;

    {
        int n = tid >> 2, quarter = tid & 3;
        int jj = n >> 2, g = n & 3;
        int grow = g * HH + ng * 32 + jj;
        for (int k = quarter * 64; k < quarter * 64 + 64; k++) {
            wh[n * KPD + k] = __float2half_rn(g_Wcomb[grow * HH + k]);
        }
    }
    __syncthreads();
    const int kbase = wg * 128;
    const int rB = wsub * 16 + (lane & 7) + ((lane >= 16) ? 8 : 0);
    const int cB = (lane & 8) ? 8 : 0;
    const __half* bph = wh + rB * KPD + cB + kbase;
    uint32_t Bf[8][4];
#pragma unroll
    for (int ks = 0; ks < 8; ks++) ldm4(Bf[ks], bph + ks * 16);

    const int b_loc = w;
    const int j = lane;
    const int col = ng * 32 + j;
    float bias[4], d0v[4];
#pragma unroll
    for (int g = 0; g < 4; g++) {
        int row = g * HH + col;
        bias[g] = g_bcomb[row];
        d0v[g] = g_delta0[(bg * BT + b_loc) * G4H + row];
    }
    float c0 = g_decC0[(bg * BT + b_loc) * HH + col];

    const int rA = (lane & 7) + ((lane & 8) ? 8 : 0);
    const int cA = (lane >> 4) * 8;
    const __half* aph = ah + rA * KPD + cA + kbase;
    const __half* apl = al + rA * KPD + cA + kbase;

    unsigned* ctr = &g_bar[16 + bg];
    float* mygates = wg ? gates1 : gates0;

    for (int t = 0; t < SS; t++) {
        if (t > 0 && tid == 0) {
            unsigned tgt = 8u * (unsigned)t;
            while (acq_ld(ctr) < tgt) {}
        }
        __syncthreads();
        for (int idx = tid; idx < 16 * 32; idx += 512) {
            int b = idx >> 5, q = idx & 31;
            if (t > 0) {
                size_t off = ((size_t)(t - 1) * BB + bg * BT + b) * HH;
                *(uint4*)(ah + b * KPD + q * 8) = ((const uint4*)(g_Hh + off))[q];
                *(uint4*)(al + b * KPD + q * 8) = ((const uint4*)(g_Hl + off))[q];
            } else {
                const float* p = g_decH0 + (size_t)(bg * BT + b) * HH + q * 8;
#pragma unroll
                for (int e = 0; e < 8; e++) {
                    __half hv, lv; split2h(p[e], hv, lv);
                    ah[b * KPD + q * 8 + e] = hv;
                    al[b * KPD + q * 8 + e] = lv;
                }
            }
        }
        __syncthreads();

        float dA0[4] = {0, 0, 0, 0}, dA1[4] = {0, 0, 0, 0};
        float dB0[4] = {0, 0, 0, 0}, dB1[4] = {0, 0, 0, 0};
#pragma unroll
        for (int ks = 0; ks < 8; ks++) {
            uint32_t A0[4], A1[4];
            ldm4(A0, aph + ks * 16);
            ldm4(A1, apl + ks * 16);
            mma16816(dA0, A0, Bf[ks][0], Bf[ks][1]);
            mma16816(dA1, A0, Bf[ks][2], Bf[ks][3]);
            mma16816(dB0, A1, Bf[ks][0], Bf[ks][1]);
            mma16816(dB1, A1, Bf[ks][2], Bf[ks][3]);
        }
        {
            int g = lane >> 2, tg = lane & 3;
            int cc = wsub * 16 + tg * 2;
            *(float2*)(mygates + g * 132 + cc)          = make_float2(dA0[0] + dB0[0], dA0[1] + dB0[1]);
            *(float2*)(mygates + (g + 8) * 132 + cc)    = make_float2(dA0[2] + dB0[2], dA0[3] + dB0[3]);
            *(float2*)(mygates + g * 132 + cc + 8)      = make_float2(dA1[0] + dB1[0], dA1[1] + dB1[1]);
            *(float2*)(mygates + (g + 8) * 132 + cc + 8)= make_float2(dA1[2] + dB1[2], dA1[3] + dB1[3]);
        }
        __syncthreads();
        {
            float4 gv0 = *(float4*)(gates0 + b_loc * 132 + j * 4);
            float4 gv1 = *(float4*)(gates1 + b_loc * 132 + j * 4);
            float e00 = bias[0], e01 = bias[1], e02 = bias[2], e03 = bias[3];
            if (t == 0) { e00 -= d0v[0]; e01 -= d0v[1]; e02 -= d0v[2]; e03 -= d0v[3]; }
            float i0 = sigf(gv0.x + gv1.x + e00);
            float f0 = sigf(gv0.y + gv1.y + e01);
            float gg0 = ftanh(gv0.z + gv1.z + e02);
            float o0 = sigf(gv0.w + gv1.w + e03);
            c0 = f0 * c0 + i0 * gg0;
            float hh0 = o0 * ftanh(c0);
            size_t oi = (size_t)t * BB * HH + (size_t)(bg * BT + b_loc) * HH + col;
            __half hv, lv;
            split2h(hh0, hv, lv);
            g_Hh[oi] = hv; g_Hl[oi] = lv;
        }
        __syncthreads();
        if (tid == 0) rel_inc(ctr);
    }
}

// ---------------- K4: reconstruction GEMM ----------------
#define K4R 64
__global__ __launch_bounds__(256)
void k4_out(const float* __restrict__ out_W, const float* __restrict__ out_b,
            float* __restrict__ rec) {
    extern __shared__ float sm[];
    float* ws = sm;              // [k][f]
    float* hs = sm + HH * FF;    // [k][r] stride 65
    const int tid = threadIdx.x;
    const int m0 = blockIdx.x * K4R;
    for (int idx = tid; idx < HH * FF; idx += 256) {
        int k = idx >> 6, f = idx & 63;
        ws[idx] = out_W[f * HH + k];
    }
    for (int idx = tid; idx < K4R * (HH / 2); idx += 256) {
        int r = idx >> 7, kk = (idx & 127) * 2;
        size_t off = (size_t)(m0 + r) * HH + kk;
        __half2 vh = *(const __half2*)(g_Hh + off);
        __half2 vl = *(const __half2*)(g_Hl + off);
        hs[kk * 65 + r]       = __half2float(__low2half(vh)) + __half2float(__low2half(vl));
        hs[(kk + 1) * 65 + r] = __half2float(__high2half(vh)) + __half2float(__high2half(vl));
    }
    __syncthreads();
    const int rg = tid >> 4, cg = tid & 15;
    float acc[4][4];
#pragma unroll
    for (int r = 0; r < 4; r++)
#pragma unroll
        for (int c = 0; c < 4; c++) acc[r][c] = 0.f;
#pragma unroll 4
    for (int k = 0; k < HH; k++) {
        float4 wv = *(const float4*)(ws + k * FF + cg * 4);
        float h0 = hs[k * 65 + rg * 4 + 0];
        float h1 = hs[k * 65 + rg * 4 + 1];
        float h2 = hs[k * 65 + rg * 4 + 2];
        float h3 = hs[k * 65 + rg * 4 + 3];
        acc[0][0] += h0 * wv.x; acc[0][1] += h0 * wv.y; acc[0][2] += h0 * wv.z; acc[0][3] += h0 * wv.w;
        acc[1][0] += h1 * wv.x; acc[1][1] += h1 * wv.y; acc[1][2] += h1 * wv.z; acc[1][3] += h1 * wv.w;
        acc[2][0] += h2 * wv.x; acc[2][1] += h2 * wv.y; acc[2][2] += h2 * wv.z; acc[2][3] += h2 * wv.w;
        acc[3][0] += h3 * wv.x; acc[3][1] += h3 * wv.y; acc[3][2] += h3 * wv.z; acc[3][3] += h3 * wv.w;
    }
    float ob0 = out_b[cg * 4 + 0], ob1 = out_b[cg * 4 + 1], ob2 = out_b[cg * 4 + 2], ob3 = out_b[cg * 4 + 3];
    const int t = m0 >> 8;
    const int bbase = m0 & 255;
#pragma unroll
    for (int r = 0; r < 4; r++) {
        int bb = bbase + rg * 4 + r;
        float4 o = make_float4(acc[r][0] + ob0, acc[r][1] + ob1, acc[r][2] + ob2, acc[r][3] + ob3);
        *(float4*)&rec[((size_t)bb * SS + t) * FF + cg * 4] = o;
    }
}

// ---------------- launch ----------------
extern "C" void kernel_launch(void* const* d_in, const int* in_sizes, int n_in,
                              void* d_out, int out_size) {
    const float* x        = (const float*)d_in[0];
    const float* enc_Wih  = (const float*)d_in[1];
    const float* enc_Whh  = (const float*)d_in[2];
    const float* enc_bih  = (const float*)d_in[3];
    const float* enc_bhh  = (const float*)d_in[4];
    const float* attn_W   = (const float*)d_in[5];
    const float* attn_b   = (const float*)d_in[6];
    const float* fc_W     = (const float*)d_in[7];
    const float* fc_b     = (const float*)d_in[8];
    const float* bn_g     = (const float*)d_in[9];
    const float* bn_be    = (const float*)d_in[10];
    const float* bn_m     = (const float*)d_in[11];
    const float* bn_v     = (const float*)d_in[12];
    const float* dh_W     = (const float*)d_in[13];
    const float* dh_b     = (const float*)d_in[14];
    const float* dc_W     = (const float*)d_in[15];
    const float* dc_b     = (const float*)d_in[16];
    const float* dec_Wih  = (const float*)d_in[17];
    const float* dec_Whh  = (const float*)d_in[18];
    const float* dec_bih  = (const float*)d_in[19];
    const float* dec_bhh  = (const float*)d_in[20];
    const float* out_W    = (const float*)d_in[21];
    const float* out_b    = (const float*)d_in[22];

    float* out = (float*)d_out;
    float* out_rec = out;
    float* out_emb = out + (size_t)BB * SS * FF;
    float* out_wt  = out_emb + (size_t)BB * EE;

    const int smem1 = 128 * KPE * 2 + 2 * 16 * KPE * 2 + 2 * 16 * 132 * 4;   // 121856
    const int smem3 = 128 * KPD * 2 + 2 * 16 * KPD * 2 + 2 * 16 * 132 * 4;   // 101376
    const int smem4 = (HH * FF + HH * 65) * 4;
    cudaFuncSetAttribute(k1_enc, cudaFuncAttributeMaxDynamicSharedMemorySize, smem1);
    cudaFuncSetAttribute(k3_dec, cudaFuncAttributeMaxDynamicSharedMemorySize, smem3);
    cudaFuncSetAttribute(k4_out, cudaFuncAttributeMaxDynamicSharedMemorySize, smem4);

    k0x<<<(BB * SS * FF) / (256 * 4), 256>>>(x);
    k0_prep<<<G4H, 256>>>(dec_Wih, dec_Whh, dec_bih, dec_bhh, out_W, out_b);
    k1_enc<<<128, 512, smem1>>>(enc_Wih, enc_Whh, enc_bih, enc_bhh, attn_W);
    k2a_softmax<<<BB, 256>>>(attn_b, out_wt);
    k2b_ctx<<<16 * BB, 256>>>();
    k2c_emb<<<BB, 256>>>(fc_W, fc_b, bn_g, bn_be, bn_m, bn_v,
                         dh_W, dh_b, dc_W, dc_b, dec_Wih, out_W, out_b, out_emb);
    k3_dec<<<128, 512, smem3>>>();
    k4_out<<<(BB * SS) / K4R, 256, smem4>>>(out_W, out_b, out_rec);
}

// round 15
// speedup vs baseline: 1.1476x; 1.1445x over previous
#include <cuda_runtime.h>
#include <cuda_fp16.h>
#include <math.h>
#include <stdint.h>

#define BB 256
#define SS 512
#define FF 64
#define HH 256
#define EE 128
#define G4H 1024
#define BT 16
#define KPE 328
#define KPD 264

// ---------------- device scratch ----------------
__device__ __half g_Hh[(size_t)SS * BB * HH];   // fp16 hi, [t][b][h] (enc then dec)
__device__ __half g_Hl[(size_t)SS * BB * HH];   // fp16 lo (k2b/k4 precision only)
__device__ __half g_xh[(size_t)BB * SS * FF];
__device__ float g_scorep[8 * BB * SS];
__device__ float g_wt[BB * SS];
__device__ float g_ctxp[16 * BB * HH];
__device__ float g_Wcomb[G4H * HH];
__device__ float g_bcomb[G4H];
__device__ float g_decH0[BB * HH];
__device__ float g_decC0[BB * HH];
__device__ float g_delta0[BB * G4H];
__device__ unsigned g_bar[32];

__device__ __forceinline__ float sigf(float v) { return 1.f / (1.f + __expf(-v)); }
__device__ __forceinline__ float ftanh(float v) {
    float e = __expf(-2.f * fabsf(v));
    float r = __fdividef(1.f - e, 1.f + e);
    return copysignf(r, v);
}

__device__ __forceinline__ void split2h(float v, __half& h, __half& l) {
    h = __float2half_rn(v);
    l = __float2half_rn(v - __half2float(h));
}

__device__ __forceinline__ void ldm4(uint32_t* r, const void* p) {
    unsigned a = (unsigned)__cvta_generic_to_shared(p);
    asm volatile("ldmatrix.sync.aligned.m8n8.x4.shared.b16 {%0,%1,%2,%3}, [%4];"
                 : "=r"(r[0]), "=r"(r[1]), "=r"(r[2]), "=r"(r[3]) : "r"(a));
}

__device__ __forceinline__ void mma16816(float* d, const uint32_t* a, uint32_t b0, uint32_t b1) {
    asm volatile("mma.sync.aligned.m16n8k16.row.col.f32.f16.f16.f32 "
                 "{%0,%1,%2,%3}, {%4,%5,%6,%7}, {%8,%9}, {%0,%1,%2,%3};"
                 : "+f"(d[0]), "+f"(d[1]), "+f"(d[2]), "+f"(d[3])
                 : "r"(a[0]), "r"(a[1]), "r"(a[2]), "r"(a[3]), "r"(b0), "r"(b1));
}

__device__ __forceinline__ void rel_inc(unsigned* p) {
    asm volatile("red.release.gpu.global.add.u32 [%0], %1;" :: "l"(p), "r"(1u) : "memory");
}
__device__ __forceinline__ unsigned acq_ld(unsigned* p) {
    unsigned v;
    asm volatile("ld.acquire.gpu.global.u32 %0, [%1];" : "=r"(v) : "l"(p) : "memory");
    return v;
}

// ---------------- K0x: split x into fp16 (hi only needed for MMA) ----------------
__global__ void k0x(const float* __restrict__ x) {
    size_t idx = (size_t)blockIdx.x * 256 + threadIdx.x;
    float4 v = ((const float4*)x)[idx];
    __half2 a = __halves2half2(__float2half_rn(v.x), __float2half_rn(v.y));
    __half2 b = __halves2half2(__float2half_rn(v.z), __float2half_rn(v.w));
    ((__half2*)g_xh)[idx * 2]     = a;
    ((__half2*)g_xh)[idx * 2 + 1] = b;
}

// ---------------- K0: decoder combined weights + zero barriers ----------------
__global__ void k0_prep(const float* __restrict__ dec_Wih, const float* __restrict__ dec_Whh,
                        const float* __restrict__ dec_bih, const float* __restrict__ dec_bhh,
                        const float* __restrict__ out_W, const float* __restrict__ out_b) {
    int row = blockIdx.x;
    int col = threadIdx.x;
    __shared__ float wi[FF];
    if (col < FF) wi[col] = dec_Wih[row * FF + col];
    __syncthreads();
    float acc = dec_Whh[row * HH + col];
#pragma unroll 8
    for (int f = 0; f < FF; f++) acc += wi[f] * out_W[f * HH + col];
    g_Wcomb[row * HH + col] = acc;
    if (col == 0) {
        float b = dec_bih[row] + dec_bhh[row];
        for (int f = 0; f < FF; f++) b += wi[f] * out_b[f];
        g_bcomb[row] = b;
    }
    if (row == 0 && col < 32) g_bar[col] = 0u;
}

// ---------------- K1: encoder recurrence (512 thr, pure fp16 MMA, B in regs) ----------------
__global__ __launch_bounds__(512, 1)
void k1_enc(const float* __restrict__ Wih, const float* __restrict__ Whh,
            const float* __restrict__ bih, const float* __restrict__ bhh,
            const float* __restrict__ attn_W) {
    extern __shared__ char smc[];
    __half* wh = (__half*)smc;              // [128][KPE] (init only)
    __half* ah = wh + 128 * KPE;            // [16][KPE]
    float* gates0 = (float*)(ah + 16 * KPE);   // [16][132]
    float* gates1 = gates0 + 16 * 132;

    const int tid = threadIdx.x;
    const int ng = blockIdx.x & 7, bg = blockIdx.x >> 3;
    const int lane = tid & 31, w = tid >> 5;
    const int wsub = w & 7, wg = w >> 3;

    // weights (fp16) -> smem, then hoist B fragments to registers
    {
        int n = tid >> 2, quarter = tid & 3;
        int jj = n >> 2, g = n & 3;
        int grow = g * HH + ng * 32 + jj;
        for (int k = quarter * 80; k < quarter * 80 + 80; k++) {
            float wv = (k < HH) ? Whh[grow * HH + k] : Wih[grow * FF + (k - HH)];
            wh[n * KPE + k] = __float2half_rn(wv);
        }
    }
    __syncthreads();
    const int kbase = wg * 160;
    const int rB = wsub * 16 + (lane & 7) + ((lane >= 16) ? 8 : 0);
    const int cB = (lane & 8) ? 8 : 0;
    const __half* bph = wh + rB * KPE + cB + kbase;
    uint32_t Bf[10][4];
#pragma unroll
    for (int ks = 0; ks < 10; ks++) ldm4(Bf[ks], bph + ks * 16);

    const int b_loc = w;
    const int j = lane;
    const int col = ng * 32 + j;
    float bias[4];
#pragma unroll
    for (int g = 0; g < 4; g++) bias[g] = bih[g * HH + col] + bhh[g * HH + col];
    const float aw_j = attn_W[col];

    const int rA = (lane & 7) + ((lane & 8) ? 8 : 0);
    const int cA = (lane >> 4) * 8;
    const __half* aph = ah + rA * KPE + cA + kbase;

    float c0 = 0.f;
    unsigned* ctr = &g_bar[bg];
    float* mygates = wg ? gates1 : gates0;

    for (int t = 0; t < SS; t++) {
        if (t > 0 && tid == 0) {
            unsigned tgt = 8u * (unsigned)t;
            while (acq_ld(ctr) < tgt) {}
        }
        __syncthreads();
        // A-build: 16 rows x 40 chunks (hi only)
        for (int idx = tid; idx < 16 * 40; idx += 512) {
            int b = idx / 40, q = idx - b * 40;
            uint4 vh;
            if (q < 32) {
                if (t > 0) {
                    size_t off = ((size_t)(t - 1) * BB + bg * BT + b) * HH;
                    vh = ((const uint4*)(g_Hh + off))[q];
                } else {
                    vh = make_uint4(0, 0, 0, 0);
                }
            } else {
                size_t off = ((size_t)(bg * BT + b) * SS + t) * FF;
                vh = ((const uint4*)(g_xh + off))[q - 32];
            }
            *(uint4*)(ah + b * KPE + q * 8) = vh;
        }
        __syncthreads();

        float dA0[4] = {0, 0, 0, 0}, dA1[4] = {0, 0, 0, 0};
#pragma unroll
        for (int ks = 0; ks < 10; ks++) {
            uint32_t A0[4];
            ldm4(A0, aph + ks * 16);
            mma16816(dA0, A0, Bf[ks][0], Bf[ks][1]);
            mma16816(dA1, A0, Bf[ks][2], Bf[ks][3]);
        }
        {
            int g = lane >> 2, tg = lane & 3;
            int cc = wsub * 16 + tg * 2;
            *(float2*)(mygates + g * 132 + cc)          = make_float2(dA0[0], dA0[1]);
            *(float2*)(mygates + (g + 8) * 132 + cc)    = make_float2(dA0[2], dA0[3]);
            *(float2*)(mygates + g * 132 + cc + 8)      = make_float2(dA1[0], dA1[1]);
            *(float2*)(mygates + (g + 8) * 132 + cc + 8)= make_float2(dA1[2], dA1[3]);
        }
        __syncthreads();
        {
            float4 gv0 = *(float4*)(gates0 + b_loc * 132 + j * 4);
            float4 gv1 = *(float4*)(gates1 + b_loc * 132 + j * 4);
            float i0 = sigf(gv0.x + gv1.x + bias[0]);
            float f0 = sigf(gv0.y + gv1.y + bias[1]);
            float gg0 = ftanh(gv0.z + gv1.z + bias[2]);
            float o0 = sigf(gv0.w + gv1.w + bias[3]);
            c0 = f0 * c0 + i0 * gg0;
            float hh0 = o0 * ftanh(c0);
            size_t oi = (size_t)t * BB * HH + (size_t)(bg * BT + b_loc) * HH + col;
            __half hv, lv;
            split2h(hh0, hv, lv);
            g_Hh[oi] = hv; g_Hl[oi] = lv;
            float s0 = hh0 * aw_j;
#pragma unroll
            for (int o = 16; o; o >>= 1) s0 += __shfl_xor_sync(~0u, s0, o);
            if (lane == 0)
                g_scorep[(size_t)ng * BB * SS + (size_t)(bg * BT + b_loc) * SS + t] = s0;
        }
        __syncthreads();
        if (tid == 0) rel_inc(ctr);
    }
}

// ---------------- K2a: softmax ----------------
__global__ __launch_bounds__(256)
void k2a_softmax(const float* __restrict__ attn_b, float* __restrict__ out_wt) {
    int b = blockIdx.x, tid = threadIdx.x;
    __shared__ float sc[SS];
    __shared__ float red[8];
    const float ab = attn_b[0];
    for (int tt = tid; tt < SS; tt += 256) {
        float s = ab;
#pragma unroll
        for (int ng = 0; ng < 8; ng++)
            s += g_scorep[(size_t)ng * BB * SS + (size_t)b * SS + tt];
        sc[tt] = s;
    }
    __syncthreads();
    float m = -1e30f;
    for (int tt = tid; tt < SS; tt += 256) m = fmaxf(m, sc[tt]);
    for (int o = 16; o; o >>= 1) m = fmaxf(m, __shfl_xor_sync(~0u, m, o));
    if ((tid & 31) == 0) red[tid >> 5] = m;
    __syncthreads();
    if (tid < 8) {
        float mm = red[tid];
        for (int o = 4; o; o >>= 1) mm = fmaxf(mm, __shfl_xor_sync(0xff, mm, o));
        if (tid == 0) red[0] = mm;
    }
    __syncthreads();
    m = red[0];
    __syncthreads();
    float lsum = 0.f;
    for (int tt = tid; tt < SS; tt += 256) { float e = expf(sc[tt] - m); sc[tt] = e; lsum += e; }
    for (int o = 16; o; o >>= 1) lsum += __shfl_xor_sync(~0u, lsum, o);
    if ((tid & 31) == 0) red[tid >> 5] = lsum;
    __syncthreads();
    if (tid < 8) {
        float ss = red[tid];
        for (int o = 4; o; o >>= 1) ss += __shfl_xor_sync(0xff, ss, o);
        if (tid == 0) red[0] = ss;
    }
    __syncthreads();
    float inv = 1.f / red[0];
    for (int tt = tid; tt < SS; tt += 256) {
        float wv = sc[tt] * inv;
        g_wt[b * SS + tt] = wv;
        out_wt[b * SS + tt] = wv;
    }
}

// ---------------- K2b: context partials (16 t-chunks per batch) ----------------
__global__ __launch_bounds__(256)
void k2b_ctx() {
    int b = blockIdx.x & 255, ch = blockIdx.x >> 8, tid = threadIdx.x;
    __shared__ float ws[32];
    if (tid < 32) ws[tid] = g_wt[b * SS + ch * 32 + tid];
    __syncthreads();
    float ca = 0.f;
#pragma unroll 4
    for (int i = 0; i < 32; i++) {
        int t2 = ch * 32 + i;
        size_t off = (size_t)t2 * BB * HH + (size_t)b * HH + tid;
        ca += ws[i] * (__half2float(g_Hh[off]) + __half2float(g_Hl[off]));
    }
    g_ctxp[(size_t)ch * BB * HH + b * HH + tid] = ca;
}

// ---------------- K2c: reduce context + embedding + decoder init + delta0 ----------------
__global__ __launch_bounds__(256)
void k2c_emb(const float* __restrict__ fc_W, const float* __restrict__ fc_b,
             const float* __restrict__ bn_g, const float* __restrict__ bn_be,
             const float* __restrict__ bn_m, const float* __restrict__ bn_v,
             const float* __restrict__ dh_W, const float* __restrict__ dh_b,
             const float* __restrict__ dc_W, const float* __restrict__ dc_b,
             const float* __restrict__ dec_Wih, const float* __restrict__ out_W,
             const float* __restrict__ out_b,
             float* __restrict__ out_emb) {
    int b = blockIdx.x, tid = threadIdx.x;
    __shared__ float ctx[HH];
    __shared__ float embs[EE];
    __shared__ float dhs[HH];
    __shared__ float v0s[FF];
    {
        float ca = 0.f;
#pragma unroll
        for (int ch = 0; ch < 16; ch++) ca += g_ctxp[(size_t)ch * BB * HH + b * HH + tid];
        ctx[tid] = ca;
    }
    __syncthreads();
    if (tid < EE) {
        float r = fc_b[tid];
#pragma unroll 8
        for (int k = 0; k < HH; k++) r += ctx[k] * fc_W[tid * HH + k];
        float em = tanhf((r - bn_m[tid]) * rsqrtf(bn_v[tid] + 1e-5f) * bn_g[tid] + bn_be[tid]);
        embs[tid] = em;
        out_emb[b * EE + tid] = em;
    }
    __syncthreads();
    {
        float dh = dh_b[tid], dc = dc_b[tid];
#pragma unroll 8
        for (int e = 0; e < EE; e++) { dh += embs[e] * dh_W[tid * EE + e]; dc += embs[e] * dc_W[tid * EE + e]; }
        g_decH0[b * HH + tid] = dh;
        g_decC0[b * HH + tid] = dc;
        dhs[tid] = dh;
    }
    __syncthreads();
    if (tid < FF) {
        float v = out_b[tid];
#pragma unroll 8
        for (int h = 0; h < HH; h++) v += dhs[h] * out_W[tid * HH + h];
        v0s[tid] = v;
    }
    __syncthreads();
    for (int row = tid; row < G4H; row += 256) {
        float d = 0.f;
#pragma unroll 8
        for (int f = 0; f < FF; f++) d += v0s[f] * dec_Wih[row * FF + f];
        g_delta0[b * G4H + row] = d;
    }
}

// ---------------- K3: decoder recurrence (512 thr, pure fp16 MMA, B in regs) ----------------
__global__ __launch_bounds__(512, 1)
void k3_dec() {
    extern __shared__ char smc[];
    __half* wh = (__half*)smc;              // [128][KPD] (init only)
    __half* ah = wh + 128 * KPD;            // [16][KPD]
    float* gates0 = (float*)(ah + 16 * KPD);
    float* gates1 = gates0 + 16 * 132;

    const int tid = threadIdx.x;
    const int ng = blockIdx.x & 7, bg = blockIdx.x >> 3;
    const int lane = tid & 31, w = tid >> 5;
    const int wsub = w & 7, wg = w >> 3;

    {
        int n = tid >> 2, quarter = tid & 3;
        int jj = n >> 2, g = n & 3;
        int grow = g * HH + ng * 32 + jj;
        for (int k = quarter * 64; k < quarter * 64 + 64; k++) {
            wh[n * KPD + k] = __float2half_rn(g_Wcomb[grow * HH + k]);
        }
    }
    __syncthreads();
    const int kbase = wg * 128;
    const int rB = wsub * 16 + (lane & 7) + ((lane >= 16) ? 8 : 0);
    const int cB = (lane & 8) ? 8 : 0;
    const __half* bph = wh + rB * KPD + cB + kbase;
    uint32_t Bf[8][4];
#pragma unroll
    for (int ks = 0; ks < 8; ks++) ldm4(Bf[ks], bph + ks * 16);

    const int b_loc = w;
    const int j = lane;
    const int col = ng * 32 + j;
    float bias[4], d0v[4];
#pragma unroll
    for (int g = 0; g < 4; g++) {
        int row = g * HH + col;
        bias[g] = g_bcomb[row];
        d0v[g] = g_delta0[(bg * BT + b_loc) * G4H + row];
    }
    float c0 = g_decC0[(bg * BT + b_loc) * HH + col];

    const int rA = (lane & 7) + ((lane & 8) ? 8 : 0);
    const int cA = (lane >> 4) * 8;
    const __half* aph = ah + rA * KPD + cA + kbase;

    unsigned* ctr = &g_bar[16 + bg];
    float* mygates = wg ? gates1 : gates0;

    for (int t = 0; t < SS; t++) {
        if (t > 0 && tid == 0) {
            unsigned tgt = 8u * (unsigned)t;
            while (acq_ld(ctr) < tgt) {}
        }
        __syncthreads();
        for (int idx = tid; idx < 16 * 32; idx += 512) {
            int b = idx >> 5, q = idx & 31;
            if (t > 0) {
                size_t off = ((size_t)(t - 1) * BB + bg * BT + b) * HH;
                *(uint4*)(ah + b * KPD + q * 8) = ((const uint4*)(g_Hh + off))[q];
            } else {
                const float* p = g_decH0 + (size_t)(bg * BT + b) * HH + q * 8;
#pragma unroll
                for (int e = 0; e < 8; e++)
                    ah[b * KPD + q * 8 + e] = __float2half_rn(p[e]);
            }
        }
        __syncthreads();

        float dA0[4] = {0, 0, 0, 0}, dA1[4] = {0, 0, 0, 0};
#pragma unroll
        for (int ks = 0; ks < 8; ks++) {
            uint32_t A0[4];
            ldm4(A0, aph + ks * 16);
            mma16816(dA0, A0, Bf[ks][0], Bf[ks][1]);
            mma16816(dA1, A0, Bf[ks][2], Bf[ks][3]);
        }
        {
            int g = lane >> 2, tg = lane & 3;
            int cc = wsub * 16 + tg * 2;
            *(float2*)(mygates + g * 132 + cc)          = make_float2(dA0[0], dA0[1]);
            *(float2*)(mygates + (g + 8) * 132 + cc)    = make_float2(dA0[2], dA0[3]);
            *(float2*)(mygates + g * 132 + cc + 8)      = make_float2(dA1[0], dA1[1]);
            *(float2*)(mygates + (g + 8) * 132 + cc + 8)= make_float2(dA1[2], dA1[3]);
        }
        __syncthreads();
        {
            float4 gv0 = *(float4*)(gates0 + b_loc * 132 + j * 4);
            float4 gv1 = *(float4*)(gates1 + b_loc * 132 + j * 4);
            float e00 = bias[0], e01 = bias[1], e02 = bias[2], e03 = bias[3];
            if (t == 0) { e00 -= d0v[0]; e01 -= d0v[1]; e02 -= d0v[2]; e03 -= d0v[3]; }
            float i0 = sigf(gv0.x + gv1.x + e00);
            float f0 = sigf(gv0.y + gv1.y + e01);
            float gg0 = ftanh(gv0.z + gv1.z + e02);
            float o0 = sigf(gv0.w + gv1.w + e03);
            c0 = f0 * c0 + i0 * gg0;
            float hh0 = o0 * ftanh(c0);
            size_t oi = (size_t)t * BB * HH + (size_t)(bg * BT + b_loc) * HH + col;
            __half hv, lv;
            split2h(hh0, hv, lv);
            g_Hh[oi] = hv; g_Hl[oi] = lv;
        }
        __syncthreads();
        if (tid == 0) rel_inc(ctr);
    }
}

// ---------------- K4: reconstruction GEMM ----------------
#define K4R 64
__global__ __launch_bounds__(256)
void k4_out(const float* __restrict__ out_W, const float* __restrict__ out_b,
            float* __restrict__ rec) {
    extern __shared__ float sm[];
    float* ws = sm;              // [k][f]
    float* hs = sm + HH * FF;    // [k][r] stride 65
    const int tid = threadIdx.x;
    const int m0 = blockIdx.x * K4R;
    for (int idx = tid; idx < HH * FF; idx += 256) {
        int k = idx >> 6, f = idx & 63;
        ws[idx] = out_W[f * HH + k];
    }
    for (int idx = tid; idx < K4R * (HH / 2); idx += 256) {
        int r = idx >> 7, kk = (idx & 127) * 2;
        size_t off = (size_t)(m0 + r) * HH + kk;
        __half2 vh = *(const __half2*)(g_Hh + off);
        __half2 vl = *(const __half2*)(g_Hl + off);
        hs[kk * 65 + r]       = __half2float(__low2half(vh)) + __half2float(__low2half(vl));
        hs[(kk + 1) * 65 + r] = __half2float(__high2half(vh)) + __half2float(__high2half(vl));
    }
    __syncthreads();
    const int rg = tid >> 4, cg = tid & 15;
    float acc[4][4];
#pragma unroll
    for (int r = 0; r < 4; r++)
#pragma unroll
        for (int c = 0; c < 4; c++) acc[r][c] = 0.f;
#pragma unroll 4
    for (int k = 0; k < HH; k++) {
        float4 wv = *(const float4*)(ws + k * FF + cg * 4);
        float h0 = hs[k * 65 + rg * 4 + 0];
        float h1 = hs[k * 65 + rg * 4 + 1];
        float h2 = hs[k * 65 + rg * 4 + 2];
        float h3 = hs[k * 65 + rg * 4 + 3];
        acc[0][0] += h0 * wv.x; acc[0][1] += h0 * wv.y; acc[0][2] += h0 * wv.z; acc[0][3] += h0 * wv.w;
        acc[1][0] += h1 * wv.x; acc[1][1] += h1 * wv.y; acc[1][2] += h1 * wv.z; acc[1][3] += h1 * wv.w;
        acc[2][0] += h2 * wv.x; acc[2][1] += h2 * wv.y; acc[2][2] += h2 * wv.z; acc[2][3] += h2 * wv.w;
        acc[3][0] += h3 * wv.x; acc[3][1] += h3 * wv.y; acc[3][2] += h3 * wv.z; acc[3][3] += h3 * wv.w;
    }
    float ob0 = out_b[cg * 4 + 0], ob1 = out_b[cg * 4 + 1], ob2 = out_b[cg * 4 + 2], ob3 = out_b[cg * 4 + 3];
    const int t = m0 >> 8;
    const int bbase = m0 & 255;
#pragma unroll
    for (int r = 0; r < 4; r++) {
        int bb = bbase + rg * 4 + r;
        float4 o = make_float4(acc[r][0] + ob0, acc[r][1] + ob1, acc[r][2] + ob2, acc[r][3] + ob3);
        *(float4*)&rec[((size_t)bb * SS + t) * FF + cg * 4] = o;
    }
}

// ---------------- launch ----------------
extern "C" void kernel_launch(void* const* d_in, const int* in_sizes, int n_in,
                              void* d_out, int out_size) {
    const float* x        = (const float*)d_in[0];
    const float* enc_Wih  = (const float*)d_in[1];
    const float* enc_Whh  = (const float*)d_in[2];
    const float* enc_bih  = (const float*)d_in[3];
    const float* enc_bhh  = (const float*)d_in[4];
    const float* attn_W   = (const float*)d_in[5];
    const float* attn_b   = (const float*)d_in[6];
    const float* fc_W     = (const float*)d_in[7];
    const float* fc_b     = (const float*)d_in[8];
    const float* bn_g     = (const float*)d_in[9];
    const float* bn_be    = (const float*)d_in[10];
    const float* bn_m     = (const float*)d_in[11];
    const float* bn_v     = (const float*)d_in[12];
    const float* dh_W     = (const float*)d_in[13];
    const float* dh_b     = (const float*)d_in[14];
    const float* dc_W     = (const float*)d_in[15];
    const float* dc_b     = (const float*)d_in[16];
    const float* dec_Wih  = (const float*)d_in[17];
    const float* dec_Whh  = (const float*)d_in[18];
    const float* dec_bih  = (const float*)d_in[19];
    const float* dec_bhh  = (const float*)d_in[20];
    const float* out_W    = (const float*)d_in[21];
    const float* out_b    = (const float*)d_in[22];

    float* out = (float*)d_out;
    float* out_rec = out;
    float* out_emb = out + (size_t)BB * SS * FF;
    float* out_wt  = out_emb + (size_t)BB * EE;

    const int smem1 = 128 * KPE * 2 + 16 * KPE * 2 + 2 * 16 * 132 * 4;   // 111360
    const int smem3 = 128 * KPD * 2 + 16 * KPD * 2 + 2 * 16 * 132 * 4;   // 92928
    const int smem4 = (HH * FF + HH * 65) * 4;
    cudaFuncSetAttribute(k1_enc, cudaFuncAttributeMaxDynamicSharedMemorySize, smem1);
    cudaFuncSetAttribute(k3_dec, cudaFuncAttributeMaxDynamicSharedMemorySize, smem3);
    cudaFuncSetAttribute(k4_out, cudaFuncAttributeMaxDynamicSharedMemorySize, smem4);

    k0x<<<(BB * SS * FF) / (256 * 4), 256>>>(x);
    k0_prep<<<G4H, 256>>>(dec_Wih, dec_Whh, dec_bih, dec_bhh, out_W, out_b);
    k1_enc<<<128, 512, smem1>>>(enc_Wih, enc_Whh, enc_bih, enc_bhh, attn_W);
    k2a_softmax<<<BB, 256>>>(attn_b, out_wt);
    k2b_ctx<<<16 * BB, 256>>>();
    k2c_emb<<<BB, 256>>>(fc_W, fc_b, bn_g, bn_be, bn_m, bn_v,
                         dh_W, dh_b, dc_W, dc_b, dec_Wih, out_W, out_b, out_emb);
    k3_dec<<<128, 512, smem3>>>();
    k4_out<<<(BB * SS) / K4R, 256, smem4>>>(out_W, out_b, out_rec);
}

// round 16
// speedup vs baseline: 1.1908x; 1.0377x over previous
#include <cuda_runtime.h>
#include <cuda_fp16.h>
#include <math.h>
#include <stdint.h>

#define BB 256
#define SS 512
#define FF 64
#define HH 256
#define EE 128
#define G4H 1024
#define BT 16
#define KPE 328
#define KPD 264

// ---------------- device scratch ----------------
__device__ __half g_Hh[(size_t)SS * BB * HH];   // fp16 hidden states [t][b][h] (enc then dec)
__device__ __half g_xh[(size_t)BB * SS * FF];
__device__ float g_scorep[8 * BB * SS];
__device__ float g_wt[BB * SS];
__device__ float g_ctxp[16 * BB * HH];
__device__ float g_Wcomb[G4H * HH];
__device__ float g_bcomb[G4H];
__device__ float g_decH0[BB * HH];
__device__ float g_decC0[BB * HH];
__device__ float g_delta0[BB * G4H];
__device__ unsigned g_bar[32];

__device__ __forceinline__ float sigf(float v) { return 1.f / (1.f + __expf(-v)); }
__device__ __forceinline__ float ftanh(float v) {
    float e = __expf(-2.f * fabsf(v));
    float r = __fdividef(1.f - e, 1.f + e);
    return copysignf(r, v);
}

__device__ __forceinline__ void ldm4(uint32_t* r, const void* p) {
    unsigned a = (unsigned)__cvta_generic_to_shared(p);
    asm volatile("ldmatrix.sync.aligned.m8n8.x4.shared.b16 {%0,%1,%2,%3}, [%4];"
                 : "=r"(r[0]), "=r"(r[1]), "=r"(r[2]), "=r"(r[3]) : "r"(a));
}

__device__ __forceinline__ void mma16816(float* d, const uint32_t* a, uint32_t b0, uint32_t b1) {
    asm volatile("mma.sync.aligned.m16n8k16.row.col.f32.f16.f16.f32 "
                 "{%0,%1,%2,%3}, {%4,%5,%6,%7}, {%8,%9}, {%0,%1,%2,%3};"
                 : "+f"(d[0]), "+f"(d[1]), "+f"(d[2]), "+f"(d[3])
                 : "r"(a[0]), "r"(a[1]), "r"(a[2]), "r"(a[3]), "r"(b0), "r"(b1));
}

__device__ __forceinline__ void rel_inc(unsigned* p) {
    asm volatile("red.release.gpu.global.add.u32 [%0], %1;" :: "l"(p), "r"(1u) : "memory");
}
__device__ __forceinline__ unsigned acq_ld(unsigned* p) {
    unsigned v;
    asm volatile("ld.acquire.gpu.global.u32 %0, [%1];" : "=r"(v) : "l"(p) : "memory");
    return v;
}

// ---------------- K0x: x -> fp16 ----------------
__global__ void k0x(const float* __restrict__ x) {
    size_t idx = (size_t)blockIdx.x * 256 + threadIdx.x;
    float4 v = ((const float4*)x)[idx];
    ((__half2*)g_xh)[idx * 2]     = __halves2half2(__float2half_rn(v.x), __float2half_rn(v.y));
    ((__half2*)g_xh)[idx * 2 + 1] = __halves2half2(__float2half_rn(v.z), __float2half_rn(v.w));
}

// ---------------- K0: decoder combined weights + zero barriers ----------------
__global__ void k0_prep(const float* __restrict__ dec_Wih, const float* __restrict__ dec_Whh,
                        const float* __restrict__ dec_bih, const float* __restrict__ dec_bhh,
                        const float* __restrict__ out_W, const float* __restrict__ out_b) {
    int row = blockIdx.x;
    int col = threadIdx.x;
    __shared__ float wi[FF];
    if (col < FF) wi[col] = dec_Wih[row * FF + col];
    __syncthreads();
    float acc = dec_Whh[row * HH + col];
#pragma unroll 8
    for (int f = 0; f < FF; f++) acc += wi[f] * out_W[f * HH + col];
    g_Wcomb[row * HH + col] = acc;
    if (col == 0) {
        float b = dec_bih[row] + dec_bhh[row];
        for (int f = 0; f < FF; f++) b += wi[f] * out_b[f];
        g_bcomb[row] = b;
    }
    if (row == 0 && col < 32) g_bar[col] = 0u;
}

// ---------------- K1: encoder recurrence (512 thr, pure fp16 MMA, B in regs) ----------------
__global__ __launch_bounds__(512, 1)
void k1_enc(const float* __restrict__ Wih, const float* __restrict__ Whh,
            const float* __restrict__ bih, const float* __restrict__ bhh,
            const float* __restrict__ attn_W) {
    extern __shared__ char smc[];
    __half* wh = (__half*)smc;              // [128][KPE] (init only)
    __half* ah = wh + 128 * KPE;            // [16][KPE]
    float* gates0 = (float*)(ah + 16 * KPE);   // [16][132]
    float* gates1 = gates0 + 16 * 132;

    const int tid = threadIdx.x;
    const int ng = blockIdx.x & 7, bg = blockIdx.x >> 3;
    const int lane = tid & 31, w = tid >> 5;
    const int wsub = w & 7, wg = w >> 3;

    {
        int n = tid >> 2, quarter = tid & 3;
        int jj = n >> 2, g = n & 3;
        int grow = g * HH + ng * 32 + jj;
        for (int k = quarter * 80; k < quarter * 80 + 80; k++) {
            float wv = (k < HH) ? Whh[grow * HH + k] : Wih[grow * FF + (k - HH)];
            wh[n * KPE + k] = __float2half_rn(wv);
        }
    }
    __syncthreads();
    const int kbase = wg * 160;
    const int rB = wsub * 16 + (lane & 7) + ((lane >= 16) ? 8 : 0);
    const int cB = (lane & 8) ? 8 : 0;
    const __half* bph = wh + rB * KPE + cB + kbase;
    uint32_t Bf[10][4];
#pragma unroll
    for (int ks = 0; ks < 10; ks++) ldm4(Bf[ks], bph + ks * 16);

    const int b_loc = w;
    const int j = lane;
    const int col = ng * 32 + j;
    float bias[4];
#pragma unroll
    for (int g = 0; g < 4; g++) bias[g] = bih[g * HH + col] + bhh[g * HH + col];
    const float aw_j = attn_W[col];

    const int rA = (lane & 7) + ((lane & 8) ? 8 : 0);
    const int cA = (lane >> 4) * 8;
    const __half* aph = ah + rA * KPE + cA + kbase;

    float c0 = 0.f;
    unsigned* ctr = &g_bar[bg];
    float* mygates = wg ? gates1 : gates0;

    for (int t = 0; t < SS; t++) {
        if (t > 0 && tid == 0) {
            unsigned tgt = 8u * (unsigned)t;
            while (acq_ld(ctr) < tgt) {}
        }
        __syncthreads();
        for (int idx = tid; idx < 16 * 40; idx += 512) {
            int b = idx / 40, q = idx - b * 40;
            uint4 vh;
            if (q < 32) {
                if (t > 0) {
                    size_t off = ((size_t)(t - 1) * BB + bg * BT + b) * HH;
                    vh = ((const uint4*)(g_Hh + off))[q];
                } else {
                    vh = make_uint4(0, 0, 0, 0);
                }
            } else {
                size_t off = ((size_t)(bg * BT + b) * SS + t) * FF;
                vh = ((const uint4*)(g_xh + off))[q - 32];
            }
            *(uint4*)(ah + b * KPE + q * 8) = vh;
        }
        __syncthreads();

        float dA0[4] = {0, 0, 0, 0}, dA1[4] = {0, 0, 0, 0};
#pragma unroll
        for (int ks = 0; ks < 10; ks++) {
            uint32_t A0[4];
            ldm4(A0, aph + ks * 16);
            mma16816(dA0, A0, Bf[ks][0], Bf[ks][1]);
            mma16816(dA1, A0, Bf[ks][2], Bf[ks][3]);
        }
        {
            int g = lane >> 2, tg = lane & 3;
            int cc = wsub * 16 + tg * 2;
            *(float2*)(mygates + g * 132 + cc)          = make_float2(dA0[0], dA0[1]);
            *(float2*)(mygates + (g + 8) * 132 + cc)    = make_float2(dA0[2], dA0[3]);
            *(float2*)(mygates + g * 132 + cc + 8)      = make_float2(dA1[0], dA1[1]);
            *(float2*)(mygates + (g + 8) * 132 + cc + 8)= make_float2(dA1[2], dA1[3]);
        }
        __syncthreads();
        {
            float4 gv0 = *(float4*)(gates0 + b_loc * 132 + j * 4);
            float4 gv1 = *(float4*)(gates1 + b_loc * 132 + j * 4);
            float i0 = sigf(gv0.x + gv1.x + bias[0]);
            float f0 = sigf(gv0.y + gv1.y + bias[1]);
            float gg0 = ftanh(gv0.z + gv1.z + bias[2]);
            float o0 = sigf(gv0.w + gv1.w + bias[3]);
            c0 = f0 * c0 + i0 * gg0;
            float hh0 = o0 * ftanh(c0);
            size_t oi = (size_t)t * BB * HH + (size_t)(bg * BT + b_loc) * HH + col;
            g_Hh[oi] = __float2half_rn(hh0);
            float s0 = hh0 * aw_j;
#pragma unroll
            for (int o = 16; o; o >>= 1) s0 += __shfl_xor_sync(~0u, s0, o);
            if (lane == 0)
                g_scorep[(size_t)ng * BB * SS + (size_t)(bg * BT + b_loc) * SS + t] = s0;
        }
        __syncthreads();
        if (tid == 0) rel_inc(ctr);
    }
}

// ---------------- K2a: softmax ----------------
__global__ __launch_bounds__(256)
void k2a_softmax(const float* __restrict__ attn_b, float* __restrict__ out_wt) {
    int b = blockIdx.x, tid = threadIdx.x;
    __shared__ float sc[SS];
    __shared__ float red[8];
    const float ab = attn_b[0];
    for (int tt = tid; tt < SS; tt += 256) {
        float s = ab;
#pragma unroll
        for (int ng = 0; ng < 8; ng++)
            s += g_scorep[(size_t)ng * BB * SS + (size_t)b * SS + tt];
        sc[tt] = s;
    }
    __syncthreads();
    float m = -1e30f;
    for (int tt = tid; tt < SS; tt += 256) m = fmaxf(m, sc[tt]);
    for (int o = 16; o; o >>= 1) m = fmaxf(m, __shfl_xor_sync(~0u, m, o));
    if ((tid & 31) == 0) red[tid >> 5] = m;
    __syncthreads();
    if (tid < 8) {
        float mm = red[tid];
        for (int o = 4; o; o >>= 1) mm = fmaxf(mm, __shfl_xor_sync(0xff, mm, o));
        if (tid == 0) red[0] = mm;
    }
    __syncthreads();
    m = red[0];
    __syncthreads();
    float lsum = 0.f;
    for (int tt = tid; tt < SS; tt += 256) { float e = expf(sc[tt] - m); sc[tt] = e; lsum += e; }
    for (int o = 16; o; o >>= 1) lsum += __shfl_xor_sync(~0u, lsum, o);
    if ((tid & 31) == 0) red[tid >> 5] = lsum;
    __syncthreads();
    if (tid < 8) {
        float ss = red[tid];
        for (int o = 4; o; o >>= 1) ss += __shfl_xor_sync(0xff, ss, o);
        if (tid == 0) red[0] = ss;
    }
    __syncthreads();
    float inv = 1.f / red[0];
    for (int tt = tid; tt < SS; tt += 256) {
        float wv = sc[tt] * inv;
        g_wt[b * SS + tt] = wv;
        out_wt[b * SS + tt] = wv;
    }
}

// ---------------- K2b: context partials (16 t-chunks per batch) ----------------
__global__ __launch_bounds__(256)
void k2b_ctx() {
    int b = blockIdx.x & 255, ch = blockIdx.x >> 8, tid = threadIdx.x;
    __shared__ float ws[32];
    if (tid < 32) ws[tid] = g_wt[b * SS + ch * 32 + tid];
    __syncthreads();
    float ca = 0.f;
#pragma unroll 4
    for (int i = 0; i < 32; i++) {
        int t2 = ch * 32 + i;
        size_t off = (size_t)t2 * BB * HH + (size_t)b * HH + tid;
        ca += ws[i] * __half2float(g_Hh[off]);
    }
    g_ctxp[(size_t)ch * BB * HH + b * HH + tid] = ca;
}

// ---------------- K2c: reduce context + embedding + decoder init + delta0 ----------------
__global__ __launch_bounds__(256)
void k2c_emb(const float* __restrict__ fc_W, const float* __restrict__ fc_b,
             const float* __restrict__ bn_g, const float* __restrict__ bn_be,
             const float* __restrict__ bn_m, const float* __restrict__ bn_v,
             const float* __restrict__ dh_W, const float* __restrict__ dh_b,
             const float* __restrict__ dc_W, const float* __restrict__ dc_b,
             const float* __restrict__ dec_Wih, const float* __restrict__ out_W,
             const float* __restrict__ out_b,
             float* __restrict__ out_emb) {
    int b = blockIdx.x, tid = threadIdx.x;
    __shared__ float ctx[HH];
    __shared__ float embs[EE];
    __shared__ float dhs[HH];
    __shared__ float v0s[FF];
    {
        float ca = 0.f;
#pragma unroll
        for (int ch = 0; ch < 16; ch++) ca += g_ctxp[(size_t)ch * BB * HH + b * HH + tid];
        ctx[tid] = ca;
    }
    __syncthreads();
    if (tid < EE) {
        float r = fc_b[tid];
#pragma unroll 8
        for (int k = 0; k < HH; k++) r += ctx[k] * fc_W[tid * HH + k];
        float em = tanhf((r - bn_m[tid]) * rsqrtf(bn_v[tid] + 1e-5f) * bn_g[tid] + bn_be[tid]);
        embs[tid] = em;
        out_emb[b * EE + tid] = em;
    }
    __syncthreads();
    {
        float dh = dh_b[tid], dc = dc_b[tid];
#pragma unroll 8
        for (int e = 0; e < EE; e++) { dh += embs[e] * dh_W[tid * EE + e]; dc += embs[e] * dc_W[tid * EE + e]; }
        g_decH0[b * HH + tid] = dh;
        g_decC0[b * HH + tid] = dc;
        dhs[tid] = dh;
    }
    __syncthreads();
    if (tid < FF) {
        float v = out_b[tid];
#pragma unroll 8
        for (int h = 0; h < HH; h++) v += dhs[h] * out_W[tid * HH + h];
        v0s[tid] = v;
    }
    __syncthreads();
    for (int row = tid; row < G4H; row += 256) {
        float d = 0.f;
#pragma unroll 8
        for (int f = 0; f < FF; f++) d += v0s[f] * dec_Wih[row * FF + f];
        g_delta0[b * G4H + row] = d;
    }
}

// ---------------- K3: decoder recurrence (512 thr, pure fp16 MMA, B in regs) ----------------
__global__ __launch_bounds__(512, 1)
void k3_dec() {
    extern __shared__ char smc[];
    __half* wh = (__half*)smc;              // [128][KPD] (init only)
    __half* ah = wh + 128 * KPD;            // [16][KPD]
    float* gates0 = (float*)(ah + 16 * KPD);
    float* gates1 = gates0 + 16 * 132;

    const int tid = threadIdx.x;
    const int ng = blockIdx.x & 7, bg = blockIdx.x >> 3;
    const int lane = tid & 31, w = tid >> 5;
    const int wsub = w & 7, wg = w >> 3;

    {
        int n = tid >> 2, quarter = tid & 3;
        int jj = n >> 2, g = n & 3;
        int grow = g * HH + ng * 32 + jj;
        for (int k = quarter * 64; k < quarter * 64 + 64; k++) {
            wh[n * KPD + k] = __float2half_rn(g_Wcomb[grow * HH + k]);
        }
    }
    __syncthreads();
    const int kbase = wg * 128;
    const int rB = wsub * 16 + (lane & 7) + ((lane >= 16) ? 8 : 0);
    const int cB = (lane & 8) ? 8 : 0;
    const __half* bph = wh + rB * KPD + cB + kbase;
    uint32_t Bf[8][4];
#pragma unroll
    for (int ks = 0; ks < 8; ks++) ldm4(Bf[ks], bph + ks * 16);

    const int b_loc = w;
    const int j = lane;
    const int col = ng * 32 + j;
    float bias[4], d0v[4];
#pragma unroll
    for (int g = 0; g < 4; g++) {
        int row = g * HH + col;
        bias[g] = g_bcomb[row];
        d0v[g] = g_delta0[(bg * BT + b_loc) * G4H + row];
    }
    float c0 = g_decC0[(bg * BT + b_loc) * HH + col];

    const int rA = (lane & 7) + ((lane & 8) ? 8 : 0);
    const int cA = (lane >> 4) * 8;
    const __half* aph = ah + rA * KPD + cA + kbase;

    unsigned* ctr = &g_bar[16 + bg];
    float* mygates = wg ? gates1 : gates0;

    for (int t = 0; t < SS; t++) {
        if (t > 0 && tid == 0) {
            unsigned tgt = 8u * (unsigned)t;
            while (acq_ld(ctr) < tgt) {}
        }
        __syncthreads();
        for (int idx = tid; idx < 16 * 32; idx += 512) {
            int b = idx >> 5, q = idx & 31;
            if (t > 0) {
                size_t off = ((size_t)(t - 1) * BB + bg * BT + b) * HH;
                *(uint4*)(ah + b * KPD + q * 8) = ((const uint4*)(g_Hh + off))[q];
            } else {
                const float* p = g_decH0 + (size_t)(bg * BT + b) * HH + q * 8;
#pragma unroll
                for (int e = 0; e < 8; e++)
                    ah[b * KPD + q * 8 + e] = __float2half_rn(p[e]);
            }
        }
        __syncthreads();

        float dA0[4] = {0, 0, 0, 0}, dA1[4] = {0, 0, 0, 0};
#pragma unroll
        for (int ks = 0; ks < 8; ks++) {
            uint32_t A0[4];
            ldm4(A0, aph + ks * 16);
            mma16816(dA0, A0, Bf[ks][0], Bf[ks][1]);
            mma16816(dA1, A0, Bf[ks][2], Bf[ks][3]);
        }
        {
            int g = lane >> 2, tg = lane & 3;
            int cc = wsub * 16 + tg * 2;
            *(float2*)(mygates + g * 132 + cc)          = make_float2(dA0[0], dA0[1]);
            *(float2*)(mygates + (g + 8) * 132 + cc)    = make_float2(dA0[2], dA0[3]);
            *(float2*)(mygates + g * 132 + cc + 8)      = make_float2(dA1[0], dA1[1]);
            *(float2*)(mygates + (g + 8) * 132 + cc + 8)= make_float2(dA1[2], dA1[3]);
        }
        __syncthreads();
        {
            float4 gv0 = *(float4*)(gates0 + b_loc * 132 + j * 4);
            float4 gv1 = *(float4*)(gates1 + b_loc * 132 + j * 4);
            float e00 = bias[0], e01 = bias[1], e02 = bias[2], e03 = bias[3];
            if (t == 0) { e00 -= d0v[0]; e01 -= d0v[1]; e02 -= d0v[2]; e03 -= d0v[3]; }
            float i0 = sigf(gv0.x + gv1.x + e00);
            float f0 = sigf(gv0.y + gv1.y + e01);
            float gg0 = ftanh(gv0.z + gv1.z + e02);
            float o0 = sigf(gv0.w + gv1.w + e03);
            c0 = f0 * c0 + i0 * gg0;
            float hh0 = o0 * ftanh(c0);
            size_t oi = (size_t)t * BB * HH + (size_t)(bg * BT + b_loc) * HH + col;
            g_Hh[oi] = __float2half_rn(hh0);
        }
        __syncthreads();
        if (tid == 0) rel_inc(ctr);
    }
}

// ---------------- K4: reconstruction GEMM (fp16 h) ----------------
#define K4R 64
__global__ __launch_bounds__(256)
void k4_out(const float* __restrict__ out_W, const float* __restrict__ out_b,
            float* __restrict__ rec) {
    extern __shared__ float sm[];
    float* ws = sm;              // [k][f]
    float* hs = sm + HH * FF;    // [k][r] stride 65
    const int tid = threadIdx.x;
    const int m0 = blockIdx.x * K4R;
    for (int idx = tid; idx < HH * FF; idx += 256) {
        int k = idx >> 6, f = idx & 63;
        ws[idx] = out_W[f * HH + k];
    }
    for (int idx = tid; idx < K4R * (HH / 2); idx += 256) {
        int r = idx >> 7, kk = (idx & 127) * 2;
        size_t off = (size_t)(m0 + r) * HH + kk;
        __half2 vh = *(const __half2*)(g_Hh + off);
        hs[kk * 65 + r]       = __half2float(__low2half(vh));
        hs[(kk + 1) * 65 + r] = __half2float(__high2half(vh));
    }
    __syncthreads();
    const int rg = tid >> 4, cg = tid & 15;
    float acc[4][4];
#pragma unroll
    for (int r = 0; r < 4; r++)
#pragma unroll
        for (int c = 0; c < 4; c++) acc[r][c] = 0.f;
#pragma unroll 4
    for (int k = 0; k < HH; k++) {
        float4 wv = *(const float4*)(ws + k * FF + cg * 4);
        float h0 = hs[k * 65 + rg * 4 + 0];
        float h1 = hs[k * 65 + rg * 4 + 1];
        float h2 = hs[k * 65 + rg * 4 + 2];
        float h3 = hs[k * 65 + rg * 4 + 3];
        acc[0][0] += h0 * wv.x; acc[0][1] += h0 * wv.y; acc[0][2] += h0 * wv.z; acc[0][3] += h0 * wv.w;
        acc[1][0] += h1 * wv.x; acc[1][1] += h1 * wv.y; acc[1][2] += h1 * wv.z; acc[1][3] += h1 * wv.w;
        acc[2][0] += h2 * wv.x; acc[2][1] += h2 * wv.y; acc[2][2] += h2 * wv.z; acc[2][3] += h2 * wv.w;
        acc[3][0] += h3 * wv.x; acc[3][1] += h3 * wv.y; acc[3][2] += h3 * wv.z; acc[3][3] += h3 * wv.w;
    }
    float ob0 = out_b[cg * 4 + 0], ob1 = out_b[cg * 4 + 1], ob2 = out_b[cg * 4 + 2], ob3 = out_b[cg * 4 + 3];
    const int t = m0 >> 8;
    const int bbase = m0 & 255;
#pragma unroll
    for (int r = 0; r < 4; r++) {
        int bb = bbase + rg * 4 + r;
        float4 o = make_float4(acc[r][0] + ob0, acc[r][1] + ob1, acc[r][2] + ob2, acc[r][3] + ob3);
        *(float4*)&rec[((size_t)bb * SS + t) * FF + cg * 4] = o;
    }
}

// ---------------- launch ----------------
extern "C" void kernel_launch(void* const* d_in, const int* in_sizes, int n_in,
                              void* d_out, int out_size) {
    const float* x        = (const float*)d_in[0];
    const float* enc_Wih  = (const float*)d_in[1];
    const float* enc_Whh  = (const float*)d_in[2];
    const float* enc_bih  = (const float*)d_in[3];
    const float* enc_bhh  = (const float*)d_in[4];
    const float* attn_W   = (const float*)d_in[5];
    const float* attn_b   = (const float*)d_in[6];
    const float* fc_W     = (const float*)d_in[7];
    const float* fc_b     = (const float*)d_in[8];
    const float* bn_g     = (const float*)d_in[9];
    const float* bn_be    = (const float*)d_in[10];
    const float* bn_m     = (const float*)d_in[11];
    const float* bn_v     = (const float*)d_in[12];
    const float* dh_W     = (const float*)d_in[13];
    const float* dh_b     = (const float*)d_in[14];
    const float* dc_W     = (const float*)d_in[15];
    const float* dc_b     = (const float*)d_in[16];
    const float* dec_Wih  = (const float*)d_in[17];
    const float* dec_Whh  = (const float*)d_in[18];
    const float* dec_bih  = (const float*)d_in[19];
    const float* dec_bhh  = (const float*)d_in[20];
    const float* out_W    = (const float*)d_in[21];
    const float* out_b    = (const float*)d_in[22];

    float* out = (float*)d_out;
    float* out_rec = out;
    float* out_emb = out + (size_t)BB * SS * FF;
    float* out_wt  = out_emb + (size_t)BB * EE;

    const int smem1 = 128 * KPE * 2 + 16 * KPE * 2 + 2 * 16 * 132 * 4;   // 111360
    const int smem3 = 128 * KPD * 2 + 16 * KPD * 2 + 2 * 16 * 132 * 4;   // 92928
    const int smem4 = (HH * FF + HH * 65) * 4;
    cudaFuncSetAttribute(k1_enc, cudaFuncAttributeMaxDynamicSharedMemorySize, smem1);
    cudaFuncSetAttribute(k3_dec, cudaFuncAttributeMaxDynamicSharedMemorySize, smem3);
    cudaFuncSetAttribute(k4_out, cudaFuncAttributeMaxDynamicSharedMemorySize, smem4);

    k0x<<<(BB * SS * FF) / (256 * 4), 256>>>(x);
    k0_prep<<<G4H, 256>>>(dec_Wih, dec_Whh, dec_bih, dec_bhh, out_W, out_b);
    k1_enc<<<128, 512, smem1>>>(enc_Wih, enc_Whh, enc_bih, enc_bhh, attn_W);
    k2a_softmax<<<BB, 256>>>(attn_b, out_wt);
    k2b_ctx<<<16 * BB, 256>>>();
    k2c_emb<<<BB, 256>>>(fc_W, fc_b, bn_g, bn_be, bn_m, bn_v,
                         dh_W, dh_b, dc_W, dc_b, dec_Wih, out_W, out_b, out_emb);
    k3_dec<<<128, 512, smem3>>>();
    k4_out<<<(BB * SS) / K4R, 256, smem4>>>(out_W, out_b, out_rec);
}

// round 17
// speedup vs baseline: 1.2843x; 1.0785x over previous
#include <cuda_runtime.h>
#include <cuda_fp16.h>
#include <math.h>
#include <stdint.h>

#define BB 256
#define SS 512
#define FF 64
#define HH 256
#define EE 128
#define G4H 1024
#define BT 16
#define KPE 328
#define KPD 264

// ---------------- device scratch ----------------
__device__ __half g_Hh[(size_t)SS * BB * HH];   // fp16 hidden states [t][b][h] (enc then dec)
__device__ __half g_xh[(size_t)BB * SS * FF];
__device__ float g_scorep[8 * BB * SS];
__device__ float g_wt[BB * SS];
__device__ float g_ctxp[16 * BB * HH];
__device__ float g_Wcomb[G4H * HH];
__device__ float g_bcomb[G4H];
__device__ float g_decH0[BB * HH];
__device__ float g_decC0[BB * HH];
__device__ float g_delta0[BB * G4H];
__device__ unsigned g_bar[32];

__device__ __forceinline__ float sigf(float v) { return 1.f / (1.f + __expf(-v)); }
__device__ __forceinline__ float ftanh(float v) {
    float e = __expf(-2.f * fabsf(v));
    float r = __fdividef(1.f - e, 1.f + e);
    return copysignf(r, v);
}

__device__ __forceinline__ void split2h(float v, __half& h, __half& l) {
    h = __float2half_rn(v);
    l = __float2half_rn(v - __half2float(h));
}

__device__ __forceinline__ void ldm4(uint32_t* r, const void* p) {
    unsigned a = (unsigned)__cvta_generic_to_shared(p);
    asm volatile("ldmatrix.sync.aligned.m8n8.x4.shared.b16 {%0,%1,%2,%3}, [%4];"
                 : "=r"(r[0]), "=r"(r[1]), "=r"(r[2]), "=r"(r[3]) : "r"(a));
}

__device__ __forceinline__ void mma16816(float* d, const uint32_t* a, uint32_t b0, uint32_t b1) {
    asm volatile("mma.sync.aligned.m16n8k16.row.col.f32.f16.f16.f32 "
                 "{%0,%1,%2,%3}, {%4,%5,%6,%7}, {%8,%9}, {%0,%1,%2,%3};"
                 : "+f"(d[0]), "+f"(d[1]), "+f"(d[2]), "+f"(d[3])
                 : "r"(a[0]), "r"(a[1]), "r"(a[2]), "r"(a[3]), "r"(b0), "r"(b1));
}

__device__ __forceinline__ void rel_inc(unsigned* p) {
    asm volatile("red.release.gpu.global.add.u32 [%0], %1;" :: "l"(p), "r"(1u) : "memory");
}
__device__ __forceinline__ unsigned acq_ld(unsigned* p) {
    unsigned v;
    asm volatile("ld.acquire.gpu.global.u32 %0, [%1];" : "=r"(v) : "l"(p) : "memory");
    return v;
}

// ---------------- K0x: x -> fp16 ----------------
__global__ void k0x(const float* __restrict__ x) {
    size_t idx = (size_t)blockIdx.x * 256 + threadIdx.x;
    float4 v = ((const float4*)x)[idx];
    ((__half2*)g_xh)[idx * 2]     = __halves2half2(__float2half_rn(v.x), __float2half_rn(v.y));
    ((__half2*)g_xh)[idx * 2 + 1] = __halves2half2(__float2half_rn(v.z), __float2half_rn(v.w));
}

// ---------------- K0: decoder combined weights + zero barriers ----------------
__global__ void k0_prep(const float* __restrict__ dec_Wih, const float* __restrict__ dec_Whh,
                        const float* __restrict__ dec_bih, const float* __restrict__ dec_bhh,
                        const float* __restrict__ out_W, const float* __restrict__ out_b) {
    int row = blockIdx.x;
    int col = threadIdx.x;
    __shared__ float wi[FF];
    if (col < FF) wi[col] = dec_Wih[row * FF + col];
    __syncthreads();
    float acc = dec_Whh[row * HH + col];
#pragma unroll 8
    for (int f = 0; f < FF; f++) acc += wi[f] * out_W[f * HH + col];
    g_Wcomb[row * HH + col] = acc;
    if (col == 0) {
        float b = dec_bih[row] + dec_bhh[row];
        for (int f = 0; f < FF; f++) b += wi[f] * out_b[f];
        g_bcomb[row] = b;
    }
    if (row == 0 && col < 32) g_bar[col] = 0u;
}

// ---------------- K1: encoder recurrence (512 thr, pure fp16 MMA, B in regs) ----------------
__global__ __launch_bounds__(512, 1)
void k1_enc(const float* __restrict__ Wih, const float* __restrict__ Whh,
            const float* __restrict__ bih, const float* __restrict__ bhh,
            const float* __restrict__ attn_W) {
    extern __shared__ char smc[];
    __half* wh = (__half*)smc;              // [128][KPE] (init only)
    __half* ah = wh + 128 * KPE;            // [16][KPE]
    float* gates0 = (float*)(ah + 16 * KPE);   // [16][132]
    float* gates1 = gates0 + 16 * 132;

    const int tid = threadIdx.x;
    const int ng = blockIdx.x & 7, bg = blockIdx.x >> 3;
    const int lane = tid & 31, w = tid >> 5;
    const int wsub = w & 7, wg = w >> 3;

    {
        int n = tid >> 2, quarter = tid & 3;
        int jj = n >> 2, g = n & 3;
        int grow = g * HH + ng * 32 + jj;
        for (int k = quarter * 80; k < quarter * 80 + 80; k++) {
            float wv = (k < HH) ? Whh[grow * HH + k] : Wih[grow * FF + (k - HH)];
            wh[n * KPE + k] = __float2half_rn(wv);
        }
    }
    __syncthreads();
    const int kbase = wg * 160;
    const int rB = wsub * 16 + (lane & 7) + ((lane >= 16) ? 8 : 0);
    const int cB = (lane & 8) ? 8 : 0;
    const __half* bph = wh + rB * KPE + cB + kbase;
    uint32_t Bf[10][4];
#pragma unroll
    for (int ks = 0; ks < 10; ks++) ldm4(Bf[ks], bph + ks * 16);

    const int b_loc = w;
    const int j = lane;
    const int col = ng * 32 + j;
    float bias[4];
#pragma unroll
    for (int g = 0; g < 4; g++) bias[g] = bih[g * HH + col] + bhh[g * HH + col];
    const float aw_j = attn_W[col];

    const int rA = (lane & 7) + ((lane & 8) ? 8 : 0);
    const int cA = (lane >> 4) * 8;
    const __half* aph = ah + rA * KPE + cA + kbase;

    float c0 = 0.f;
    unsigned* ctr = &g_bar[bg];
    float* mygates = wg ? gates1 : gates0;

    for (int t = 0; t < SS; t++) {
        if (t > 0 && tid == 0) {
            unsigned tgt = 8u * (unsigned)t;
            while (acq_ld(ctr) < tgt) {}
        }
        __syncthreads();
        for (int idx = tid; idx < 16 * 40; idx += 512) {
            int b = idx / 40, q = idx - b * 40;
            uint4 vh;
            if (q < 32) {
                if (t > 0) {
                    size_t off = ((size_t)(t - 1) * BB + bg * BT + b) * HH;
                    vh = ((const uint4*)(g_Hh + off))[q];
                } else {
                    vh = make_uint4(0, 0, 0, 0);
                }
            } else {
                size_t off = ((size_t)(bg * BT + b) * SS + t) * FF;
                vh = ((const uint4*)(g_xh + off))[q - 32];
            }
            *(uint4*)(ah + b * KPE + q * 8) = vh;
        }
        __syncthreads();

        float dA0[4] = {0, 0, 0, 0}, dA1[4] = {0, 0, 0, 0};
#pragma unroll
        for (int ks = 0; ks < 10; ks++) {
            uint32_t A0[4];
            ldm4(A0, aph + ks * 16);
            mma16816(dA0, A0, Bf[ks][0], Bf[ks][1]);
            mma16816(dA1, A0, Bf[ks][2], Bf[ks][3]);
        }
        {
            int g = lane >> 2, tg = lane & 3;
            int cc = wsub * 16 + tg * 2;
            *(float2*)(mygates + g * 132 + cc)          = make_float2(dA0[0], dA0[1]);
            *(float2*)(mygates + (g + 8) * 132 + cc)    = make_float2(dA0[2], dA0[3]);
            *(float2*)(mygates + g * 132 + cc + 8)      = make_float2(dA1[0], dA1[1]);
            *(float2*)(mygates + (g + 8) * 132 + cc + 8)= make_float2(dA1[2], dA1[3]);
        }
        __syncthreads();
        float hh0;
        {
            float4 gv0 = *(float4*)(gates0 + b_loc * 132 + j * 4);
            float4 gv1 = *(float4*)(gates1 + b_loc * 132 + j * 4);
            float i0 = sigf(gv0.x + gv1.x + bias[0]);
            float f0 = sigf(gv0.y + gv1.y + bias[1]);
            float gg0 = ftanh(gv0.z + gv1.z + bias[2]);
            float o0 = sigf(gv0.w + gv1.w + bias[3]);
            c0 = f0 * c0 + i0 * gg0;
            hh0 = o0 * ftanh(c0);
            size_t oi = (size_t)t * BB * HH + (size_t)(bg * BT + b_loc) * HH + col;
            g_Hh[oi] = __float2half_rn(hh0);
        }
        __syncthreads();
        if (tid == 0) rel_inc(ctr);
        // attention score partial AFTER release (k2a runs after kernel end)
        {
            float s0 = hh0 * aw_j;
#pragma unroll
            for (int o = 16; o; o >>= 1) s0 += __shfl_xor_sync(~0u, s0, o);
            if (lane == 0)
                g_scorep[(size_t)ng * BB * SS + (size_t)(bg * BT + b_loc) * SS + t] = s0;
        }
    }
}

// ---------------- K2a: softmax ----------------
__global__ __launch_bounds__(256)
void k2a_softmax(const float* __restrict__ attn_b, float* __restrict__ out_wt) {
    int b = blockIdx.x, tid = threadIdx.x;
    __shared__ float sc[SS];
    __shared__ float red[8];
    const float ab = attn_b[0];
    for (int tt = tid; tt < SS; tt += 256) {
        float s = ab;
#pragma unroll
        for (int ng = 0; ng < 8; ng++)
            s += g_scorep[(size_t)ng * BB * SS + (size_t)b * SS + tt];
        sc[tt] = s;
    }
    __syncthreads();
    float m = -1e30f;
    for (int tt = tid; tt < SS; tt += 256) m = fmaxf(m, sc[tt]);
    for (int o = 16; o; o >>= 1) m = fmaxf(m, __shfl_xor_sync(~0u, m, o));
    if ((tid & 31) == 0) red[tid >> 5] = m;
    __syncthreads();
    if (tid < 8) {
        float mm = red[tid];
        for (int o = 4; o; o >>= 1) mm = fmaxf(mm, __shfl_xor_sync(0xff, mm, o));
        if (tid == 0) red[0] = mm;
    }
    __syncthreads();
    m = red[0];
    __syncthreads();
    float lsum = 0.f;
    for (int tt = tid; tt < SS; tt += 256) { float e = expf(sc[tt] - m); sc[tt] = e; lsum += e; }
    for (int o = 16; o; o >>= 1) lsum += __shfl_xor_sync(~0u, lsum, o);
    if ((tid & 31) == 0) red[tid >> 5] = lsum;
    __syncthreads();
    if (tid < 8) {
        float ss = red[tid];
        for (int o = 4; o; o >>= 1) ss += __shfl_xor_sync(0xff, ss, o);
        if (tid == 0) red[0] = ss;
    }
    __syncthreads();
    float inv = 1.f / red[0];
    for (int tt = tid; tt < SS; tt += 256) {
        float wv = sc[tt] * inv;
        g_wt[b * SS + tt] = wv;
        out_wt[b * SS + tt] = wv;
    }
}

// ---------------- K2b: context partials (16 t-chunks per batch) ----------------
__global__ __launch_bounds__(256)
void k2b_ctx() {
    int b = blockIdx.x & 255, ch = blockIdx.x >> 8, tid = threadIdx.x;
    __shared__ float ws[32];
    if (tid < 32) ws[tid] = g_wt[b * SS + ch * 32 + tid];
    __syncthreads();
    float ca = 0.f;
#pragma unroll 4
    for (int i = 0; i < 32; i++) {
        int t2 = ch * 32 + i;
        size_t off = (size_t)t2 * BB * HH + (size_t)b * HH + tid;
        ca += ws[i] * __half2float(g_Hh[off]);
    }
    g_ctxp[(size_t)ch * BB * HH + b * HH + tid] = ca;
}

// ---------------- K2c: reduce context + embedding + decoder init + delta0 ----------------
__global__ __launch_bounds__(256)
void k2c_emb(const float* __restrict__ fc_W, const float* __restrict__ fc_b,
             const float* __restrict__ bn_g, const float* __restrict__ bn_be,
             const float* __restrict__ bn_m, const float* __restrict__ bn_v,
             const float* __restrict__ dh_W, const float* __restrict__ dh_b,
             const float* __restrict__ dc_W, const float* __restrict__ dc_b,
             const float* __restrict__ dec_Wih, const float* __restrict__ out_W,
             const float* __restrict__ out_b,
             float* __restrict__ out_emb) {
    int b = blockIdx.x, tid = threadIdx.x;
    __shared__ float ctx[HH];
    __shared__ float embs[EE];
    __shared__ float dhs[HH];
    __shared__ float v0s[FF];
    {
        float ca = 0.f;
#pragma unroll
        for (int ch = 0; ch < 16; ch++) ca += g_ctxp[(size_t)ch * BB * HH + b * HH + tid];
        ctx[tid] = ca;
    }
    __syncthreads();
    if (tid < EE) {
        float r = fc_b[tid];
#pragma unroll 8
        for (int k = 0; k < HH; k++) r += ctx[k] * fc_W[tid * HH + k];
        float em = tanhf((r - bn_m[tid]) * rsqrtf(bn_v[tid] + 1e-5f) * bn_g[tid] + bn_be[tid]);
        embs[tid] = em;
        out_emb[b * EE + tid] = em;
    }
    __syncthreads();
    {
        float dh = dh_b[tid], dc = dc_b[tid];
#pragma unroll 8
        for (int e = 0; e < EE; e++) { dh += embs[e] * dh_W[tid * EE + e]; dc += embs[e] * dc_W[tid * EE + e]; }
        g_decH0[b * HH + tid] = dh;
        g_decC0[b * HH + tid] = dc;
        dhs[tid] = dh;
    }
    __syncthreads();
    if (tid < FF) {
        float v = out_b[tid];
#pragma unroll 8
        for (int h = 0; h < HH; h++) v += dhs[h] * out_W[tid * HH + h];
        v0s[tid] = v;
    }
    __syncthreads();
    for (int row = tid; row < G4H; row += 256) {
        float d = 0.f;
#pragma unroll 8
        for (int f = 0; f < FF; f++) d += v0s[f] * dec_Wih[row * FF + f];
        g_delta0[b * G4H + row] = d;
    }
}

// ---------------- K3: decoder recurrence (512 thr, pure fp16 MMA, B in regs) ----------------
__global__ __launch_bounds__(512, 1)
void k3_dec() {
    extern __shared__ char smc[];
    __half* wh = (__half*)smc;              // [128][KPD] (init only)
    __half* ah = wh + 128 * KPD;            // [16][KPD]
    float* gates0 = (float*)(ah + 16 * KPD);
    float* gates1 = gates0 + 16 * 132;

    const int tid = threadIdx.x;
    const int ng = blockIdx.x & 7, bg = blockIdx.x >> 3;
    const int lane = tid & 31, w = tid >> 5;
    const int wsub = w & 7, wg = w >> 3;

    {
        int n = tid >> 2, quarter = tid & 3;
        int jj = n >> 2, g = n & 3;
        int grow = g * HH + ng * 32 + jj;
        for (int k = quarter * 64; k < quarter * 64 + 64; k++) {
            wh[n * KPD + k] = __float2half_rn(g_Wcomb[grow * HH + k]);
        }
    }
    __syncthreads();
    const int kbase = wg * 128;
    const int rB = wsub * 16 + (lane & 7) + ((lane >= 16) ? 8 : 0);
    const int cB = (lane & 8) ? 8 : 0;
    const __half* bph = wh + rB * KPD + cB + kbase;
    uint32_t Bf[8][4];
#pragma unroll
    for (int ks = 0; ks < 8; ks++) ldm4(Bf[ks], bph + ks * 16);

    const int b_loc = w;
    const int j = lane;
    const int col = ng * 32 + j;
    float bias[4], d0v[4];
#pragma unroll
    for (int g = 0; g < 4; g++) {
        int row = g * HH + col;
        bias[g] = g_bcomb[row];
        d0v[g] = g_delta0[(bg * BT + b_loc) * G4H + row];
    }
    float c0 = g_decC0[(bg * BT + b_loc) * HH + col];

    const int rA = (lane & 7) + ((lane & 8) ? 8 : 0);
    const int cA = (lane >> 4) * 8;
    const __half* aph = ah + rA * KPD + cA + kbase;

    unsigned* ctr = &g_bar[16 + bg];
    float* mygates = wg ? gates1 : gates0;

    for (int t = 0; t < SS; t++) {
        if (t > 0 && tid == 0) {
            unsigned tgt = 8u * (unsigned)t;
            while (acq_ld(ctr) < tgt) {}
        }
        __syncthreads();
        for (int idx = tid; idx < 16 * 32; idx += 512) {
            int b = idx >> 5, q = idx & 31;
            if (t > 0) {
                size_t off = ((size_t)(t - 1) * BB + bg * BT + b) * HH;
                *(uint4*)(ah + b * KPD + q * 8) = ((const uint4*)(g_Hh + off))[q];
            } else {
                const float* p = g_decH0 + (size_t)(bg * BT + b) * HH + q * 8;
#pragma unroll
                for (int e = 0; e < 8; e++)
                    ah[b * KPD + q * 8 + e] = __float2half_rn(p[e]);
            }
        }
        __syncthreads();

        float dA0[4] = {0, 0, 0, 0}, dA1[4] = {0, 0, 0, 0};
#pragma unroll
        for (int ks = 0; ks < 8; ks++) {
            uint32_t A0[4];
            ldm4(A0, aph + ks * 16);
            mma16816(dA0, A0, Bf[ks][0], Bf[ks][1]);
            mma16816(dA1, A0, Bf[ks][2], Bf[ks][3]);
        }
        {
            int g = lane >> 2, tg = lane & 3;
            int cc = wsub * 16 + tg * 2;
            *(float2*)(mygates + g * 132 + cc)          = make_float2(dA0[0], dA0[1]);
            *(float2*)(mygates + (g + 8) * 132 + cc)    = make_float2(dA0[2], dA0[3]);
            *(float2*)(mygates + g * 132 + cc + 8)      = make_float2(dA1[0], dA1[1]);
            *(float2*)(mygates + (g + 8) * 132 + cc + 8)= make_float2(dA1[2], dA1[3]);
        }
        __syncthreads();
        {
            float4 gv0 = *(float4*)(gates0 + b_loc * 132 + j * 4);
            float4 gv1 = *(float4*)(gates1 + b_loc * 132 + j * 4);
            float e00 = bias[0], e01 = bias[1], e02 = bias[2], e03 = bias[3];
            if (t == 0) { e00 -= d0v[0]; e01 -= d0v[1]; e02 -= d0v[2]; e03 -= d0v[3]; }
            float i0 = sigf(gv0.x + gv1.x + e00);
            float f0 = sigf(gv0.y + gv1.y + e01);
            float gg0 = ftanh(gv0.z + gv1.z + e02);
            float o0 = sigf(gv0.w + gv1.w + e03);
            c0 = f0 * c0 + i0 * gg0;
            float hh0 = o0 * ftanh(c0);
            size_t oi = (size_t)t * BB * HH + (size_t)(bg * BT + b_loc) * HH + col;
            g_Hh[oi] = __float2half_rn(hh0);
        }
        __syncthreads();
        if (tid == 0) rel_inc(ctr);
    }
}

// ---------------- K4: reconstruction GEMM, tensor cores (fp16 h, hi/lo weights) ----------------
#define K4M 128
#define K4P 264
__global__ __launch_bounds__(256)
void k4_out(const float* __restrict__ out_W, const float* __restrict__ out_b,
            float* __restrict__ rec) {
    extern __shared__ __half sm16[];
    __half* whs = sm16;                 // [64][K4P] hi
    __half* wls = whs + 64 * K4P;       // [64][K4P] lo
    __half* as_ = wls + 64 * K4P;       // [128][K4P]
    const int tid = threadIdx.x;
    const int lane = tid & 31, w = tid >> 5;
    const size_t m0 = (size_t)blockIdx.x * K4M;

    // weights -> smem (hi/lo)
    for (int idx = tid; idx < FF * HH; idx += 256) {
        int f = idx >> 8, k = idx & 255;
        __half hv, lv; split2h(out_W[f * HH + k], hv, lv);
        whs[f * K4P + k] = hv;
        wls[f * K4P + k] = lv;
    }
    // A tile: 128 rows of g_Hh
    for (int idx = tid; idx < K4M * 32; idx += 256) {
        int r = idx >> 5, q = idx & 31;
        *(uint4*)(as_ + r * K4P + q * 8) = ((const uint4*)(g_Hh + (m0 + r) * HH))[q];
    }
    __syncthreads();

    // per-warp m16 tile
    const int rAr = w * 16 + (lane & 7) + ((lane & 8) ? 8 : 0);
    const int cAr = (lane >> 4) * 8;
    const __half* aph = as_ + rAr * K4P + cAr;
    const int rBr = (lane & 7) + ((lane >= 16) ? 8 : 0);
    const int cBr = (lane & 8) ? 8 : 0;

    float acc[8][4];
#pragma unroll
    for (int n = 0; n < 8; n++)
#pragma unroll
        for (int c = 0; c < 4; c++) acc[n][c] = 0.f;

#pragma unroll 4
    for (int kt = 0; kt < 16; kt++) {
        uint32_t A0[4];
        ldm4(A0, aph + kt * 16);
#pragma unroll
        for (int cch = 0; cch < 4; cch++) {
            uint32_t Bh[4], Bl[4];
            const __half* bp = whs + (cch * 16 + rBr) * K4P + cBr + kt * 16;
            ldm4(Bh, bp);
            ldm4(Bl, bp + (size_t)64 * K4P);
            mma16816(acc[2 * cch],     A0, Bh[0], Bh[1]);
            mma16816(acc[2 * cch + 1], A0, Bh[2], Bh[3]);
            mma16816(acc[2 * cch],     A0, Bl[0], Bl[1]);
            mma16816(acc[2 * cch + 1], A0, Bl[2], Bl[3]);
        }
    }

    // epilogue: rows r0 = w*16 + lane>>2, r1 = r0+8 ; cols f = nt*8 + (lane&3)*2
    const int r0 = w * 16 + (lane >> 2), r1 = r0 + 8;
    const size_t m_r0 = m0 + r0, m_r1 = m0 + r1;
    const int b0 = (int)(m_r0 & 255), t0 = (int)(m_r0 >> 8);
    const int b1 = (int)(m_r1 & 255), t1 = (int)(m_r1 >> 8);
#pragma unroll
    for (int nt = 0; nt < 8; nt++) {
        int f = nt * 8 + (lane & 3) * 2;
        float ob0 = out_b[f], ob1 = out_b[f + 1];
        *(float2*)&rec[((size_t)b0 * SS + t0) * FF + f] = make_float2(acc[nt][0] + ob0, acc[nt][1] + ob1);
        *(float2*)&rec[((size_t)b1 * SS + t1) * FF + f] = make_float2(acc[nt][2] + ob0, acc[nt][3] + ob1);
    }
}

// ---------------- launch ----------------
extern "C" void kernel_launch(void* const* d_in, const int* in_sizes, int n_in,
                              void* d_out, int out_size) {
    const float* x        = (const float*)d_in[0];
    const float* enc_Wih  = (const float*)d_in[1];
    const float* enc_Whh  = (const float*)d_in[2];
    const float* enc_bih  = (const float*)d_in[3];
    const float* enc_bhh  = (const float*)d_in[4];
    const float* attn_W   = (const float*)d_in[5];
    const float* attn_b   = (const float*)d_in[6];
    const float* fc_W     = (const float*)d_in[7];
    const float* fc_b     = (const float*)d_in[8];
    const float* bn_g     = (const float*)d_in[9];
    const float* bn_be    = (const float*)d_in[10];
    const float* bn_m     = (const float*)d_in[11];
    const float* bn_v     = (const float*)d_in[12];
    const float* dh_W     = (const float*)d_in[13];
    const float* dh_b     = (const float*)d_in[14];
    const float* dc_W     = (const float*)d_in[15];
    const float* dc_b     = (const float*)d_in[16];
    const float* dec_Wih  = (const float*)d_in[17];
    const float* dec_Whh  = (const float*)d_in[18];
    const float* dec_bih  = (const float*)d_in[19];
    const float* dec_bhh  = (const float*)d_in[20];
    const float* out_W    = (const float*)d_in[21];
    const float* out_b    = (const float*)d_in[22];

    float* out = (float*)d_out;
    float* out_rec = out;
    float* out_emb = out + (size_t)BB * SS * FF;
    float* out_wt  = out_emb + (size_t)BB * EE;

    const int smem1 = 128 * KPE * 2 + 16 * KPE * 2 + 2 * 16 * 132 * 4;   // 111360
    const int smem3 = 128 * KPD * 2 + 16 * KPD * 2 + 2 * 16 * 132 * 4;   // 92928
    const int smem4 = (2 * 64 * K4P + 128 * K4P) * 2;                    // 135168
    cudaFuncSetAttribute(k1_enc, cudaFuncAttributeMaxDynamicSharedMemorySize, smem1);
    cudaFuncSetAttribute(k3_dec, cudaFuncAttributeMaxDynamicSharedMemorySize, smem3);
    cudaFuncSetAttribute(k4_out, cudaFuncAttributeMaxDynamicSharedMemorySize, smem4);

    k0x<<<(BB * SS * FF) / (256 * 4), 256>>>(x);
    k0_prep<<<G4H, 256>>>(dec_Wih, dec_Whh, dec_bih, dec_bhh, out_W, out_b);
    k1_enc<<<128, 512, smem1>>>(enc_Wih, enc_Whh, enc_bih, enc_bhh, attn_W);
    k2a_softmax<<<BB, 256>>>(attn_b, out_wt);
    k2b_ctx<<<16 * BB, 256>>>();
    k2c_emb<<<BB, 256>>>(fc_W, fc_b, bn_g, bn_be, bn_m, bn_v,
                         dh_W, dh_b, dc_W, dc_b, dec_Wih, out_W, out_b, out_emb);
    k3_dec<<<128, 512, smem3>>>();
    k4_out<<<(BB * SS) / K4M, 256, smem4>>>(out_W, out_b, out_rec);
}